// round 3
// baseline (speedup 1.0000x reference)
#include <cuda_runtime.h>

#define B    64
#define T    512
#define DIN  256
#define H    1024
#define G    4096   // 4*H
#define DOUT 256
#define NBLK 256

typedef unsigned long long ull;

// ---------------- device scratch ----------------
__device__ float  g_Wih0T[(size_t)DIN * G];      // [k][n] for xproj
__device__ float2 g_Wd0[(size_t)H * G];          // layer0 Whh0^T duplicated (w,w), [k][n]
__device__ float2 g_Wd1[(size_t)2 * H * G];      // layer1 [Wih1^T ; Whh1^T] duplicated, [k][n]
__device__ float  g_WlinT[(size_t)H * DOUT];     // [k][o]
__device__ float  g_b0[G];
__device__ float  g_b1[G];
__device__ float  g_xp[(size_t)T * G * B];       // [t][n][b]
__device__ float  g_h0[2][H * B];                // [u][b], ping-pong
__device__ float  g_h1[2][H * B];
__device__ float  g_c0[H * B];
__device__ float  g_c1[H * B];
__device__ float  g_h1buf[(size_t)T * H * B];    // [t][k][b]

__device__ volatile unsigned g_bar_gen;
__device__ unsigned g_bar_cnt;

// ---------------- helpers ----------------
__device__ __forceinline__ float sigm(float x) { return 1.0f / (1.0f + __expf(-x)); }
__device__ __forceinline__ float tanh_f(float x) {
    float e = __expf(-2.0f * fabsf(x));
    float t = (1.0f - e) / (1.0f + e);
    return x >= 0.0f ? t : -t;
}
__device__ __forceinline__ ull pack2(float lo, float hi) {
    ull r; asm("mov.b64 %0, {%1, %2};" : "=l"(r) : "f"(lo), "f"(hi)); return r;
}
__device__ __forceinline__ void unpack2(ull v, float& lo, float& hi) {
    asm("mov.b64 {%0, %1}, %2;" : "=f"(lo), "=f"(hi) : "l"(v));
}
__device__ __forceinline__ ull fma2(ull a, ull b, ull c) {
    ull d; asm("fma.rn.f32x2 %0, %1, %2, %3;" : "=l"(d) : "l"(a), "l"(b), "l"(c)); return d;
}

// ---------------- prep ----------------
__global__ void prep_kernel(const float* __restrict__ z,
                            const float* __restrict__ Wih0, const float* __restrict__ Whh0,
                            const float* __restrict__ bih0, const float* __restrict__ bhh0,
                            const float* __restrict__ Wih1, const float* __restrict__ Whh1,
                            const float* __restrict__ bih1, const float* __restrict__ bhh1,
                            const float* __restrict__ Wlin) {
    int stride = gridDim.x * blockDim.x;
    int tid = blockIdx.x * blockDim.x + threadIdx.x;
    if (tid == 0) { g_bar_gen = 0; g_bar_cnt = 0; }

    for (size_t i = tid; i < (size_t)DIN * G; i += stride) {
        size_t k = i / G, n = i % G;
        g_Wih0T[i] = Wih0[n * DIN + k];
    }
    for (size_t i = tid; i < (size_t)H * G; i += stride) {
        size_t k = i / G, n = i % G;
        float w = Whh0[n * H + k];
        g_Wd0[i] = make_float2(w, w);
    }
    for (size_t i = tid; i < (size_t)2 * H * G; i += stride) {
        size_t k = i / G, n = i % G;
        float w = (k < H) ? Wih1[n * H + k] : Whh1[n * H + (k - H)];
        g_Wd1[i] = make_float2(w, w);
    }
    for (size_t i = tid; i < (size_t)H * DOUT; i += stride) {
        size_t k = i / DOUT, o = i % DOUT;
        g_WlinT[i] = Wlin[o * H + k];
    }
    for (int i = tid; i < G; i += stride) {
        g_b0[i] = bih0[i] + bhh0[i];
        g_b1[i] = bih1[i] + bhh1[i];
    }
    for (int i = tid; i < H * B; i += stride) {
        int u = i >> 6, b = i & 63;
        float zv = z[b * H + u];
        g_h0[0][i] = zv;
        g_h1[0][i] = zv;
        g_c0[i] = 0.0f;
        g_c1[i] = 0.0f;
    }
}

// ---------------- xproj: g_xp[t][n][b] = b0[n] + x[b][t-1][:] . Wih0T[:][n] ----------------
__global__ __launch_bounds__(256) void xproj_kernel(const float* __restrict__ x) {
    int t = blockIdx.y;
    int n0 = blockIdx.x * 64;
    int tid = threadIdx.x;
    int w = tid >> 5, l = tid & 31;

    __shared__ float sh[64][64];
    float acc0[8], acc1[8];
#pragma unroll
    for (int i = 0; i < 8; i++) { acc0[i] = 0.0f; acc1[i] = 0.0f; }

    if (t > 0) {
        for (int k0 = 0; k0 < DIN; k0 += 64) {
            __syncthreads();
#pragma unroll
            for (int r = 0; r < 4; r++) {
                int v = tid + 256 * r;
                int b = v >> 4, kq = v & 15;
                *(float4*)&sh[b][kq * 4] =
                    *(const float4*)&x[((size_t)b * T + (t - 1)) * DIN + k0 + kq * 4];
            }
            __syncthreads();
#pragma unroll 8
            for (int kk = 0; kk < 64; kk++) {
                const float* wr = &g_Wih0T[(size_t)(k0 + kk) * G + n0];
                float wa = wr[l];
                float wb = wr[32 + l];
#pragma unroll
                for (int i = 0; i < 8; i++) {
                    float a = sh[w * 8 + i][kk];
                    acc0[i] += wa * a;
                    acc1[i] += wb * a;
                }
            }
        }
    }
    float ba = g_b0[n0 + l], bb = g_b0[n0 + 32 + l];
#pragma unroll
    for (int i = 0; i < 8; i++) { acc0[i] += ba; acc1[i] += bb; }
    // write [t][n][b]: thread owns b = w*8 .. w*8+7 for cols n0+l and n0+32+l
    float4 v;
    size_t basea = ((size_t)t * G + n0 + l) * B + w * 8;
    v = make_float4(acc0[0], acc0[1], acc0[2], acc0[3]); *(float4*)&g_xp[basea] = v;
    v = make_float4(acc0[4], acc0[5], acc0[6], acc0[7]); *(float4*)&g_xp[basea + 4] = v;
    size_t baseb = ((size_t)t * G + n0 + 32 + l) * B + w * 8;
    v = make_float4(acc1[0], acc1[1], acc1[2], acc1[3]); *(float4*)&g_xp[baseb] = v;
    v = make_float4(acc1[4], acc1[5], acc1[6], acc1[7]); *(float4*)&g_xp[baseb + 4] = v;
}

// ---------------- persistent recurrent kernel ----------------
__device__ __forceinline__ void grid_sync(unsigned target) {
    __syncthreads();
    if (threadIdx.x == 0) {
        __threadfence();
        if (atomicAdd(&g_bar_cnt, 1u) == NBLK - 1) {
            g_bar_cnt = 0;
            __threadfence();
            g_bar_gen = target;
        } else {
            while (g_bar_gen < target) {}
            __threadfence();
        }
    }
    __syncthreads();
}

__global__ __launch_bounds__(256, 2) void recur_kernel() {
    __shared__ float sh[128 * 64];   // activation chunk [k][b], 32KB
    __shared__ float sg[64 * 17];    // gate staging [b][c], padded

    int tid = threadIdx.x;
    int blk = blockIdx.x;
    int c = tid & 15;          // col within block: gate = c>>2, uu = c&3
    int bg = tid >> 4;         // 0..15
    int b0 = bg * 4;
    int u0 = blk * 4;
    int n = (c >> 2) * H + u0 + (c & 3);

    int up_uu = tid >> 6;      // 0..3
    int up_b  = tid & 63;
    int up_u  = u0 + up_uu;
    int up_idx = up_u * B + up_b;

    const float bv1 = g_b1[n];

    for (int t = 0; t < T; t++) {
        int cur = t & 1, nxt = cur ^ 1;

        // ================= layer 0 =================
        float4 xi = *(const float4*)&g_xp[((size_t)t * G + n) * B + b0];
        ull acc01 = pack2(xi.x, xi.y);
        ull acc23 = pack2(xi.z, xi.w);

        for (int chunk = 0; chunk < 8; chunk++) {
            int k0 = chunk * 128;
            __syncthreads();
#pragma unroll
            for (int r = 0; r < 8; r++) {
                int idx = tid + r * 256;   // float4 index into 128x64 chunk
                ((float4*)sh)[idx] = __ldcg(((const float4*)&g_h0[cur][(size_t)k0 * B]) + idx);
            }
            __syncthreads();
            const float2* wp = &g_Wd0[(size_t)k0 * G + n];
#pragma unroll 16
            for (int kk = 0; kk < 128; kk++) {
                ull w2 = *(const ull*)(wp + (size_t)kk * G);
                ulonglong2 a = *(const ulonglong2*)&sh[kk * B + b0];
                acc01 = fma2(w2, a.x, acc01);
                acc23 = fma2(w2, a.y, acc23);
            }
        }
        __syncthreads();
        {
            float a0, a1, a2, a3;
            unpack2(acc01, a0, a1);
            unpack2(acc23, a2, a3);
            sg[(b0 + 0) * 17 + c] = a0;
            sg[(b0 + 1) * 17 + c] = a1;
            sg[(b0 + 2) * 17 + c] = a2;
            sg[(b0 + 3) * 17 + c] = a3;
        }
        __syncthreads();
        {
            float gi = sg[up_b * 17 + 0 + up_uu];
            float gf = sg[up_b * 17 + 4 + up_uu];
            float gg = sg[up_b * 17 + 8 + up_uu];
            float go = sg[up_b * 17 + 12 + up_uu];
            float cc = sigm(gf) * g_c0[up_idx] + sigm(gi) * tanh_f(gg);
            g_c0[up_idx] = cc;
            g_h0[nxt][up_idx] = sigm(go) * tanh_f(cc);
        }
        grid_sync(2 * t + 1);

        // ================= layer 1 =================
        acc01 = pack2(bv1, bv1);
        acc23 = acc01;
        for (int seg = 0; seg < 2; seg++) {
            const float* src = seg ? g_h1[cur] : g_h0[nxt];
            const float2* wseg = &g_Wd1[(size_t)seg * H * G];
            for (int chunk = 0; chunk < 8; chunk++) {
                int k0 = chunk * 128;
                __syncthreads();
#pragma unroll
                for (int r = 0; r < 8; r++) {
                    int idx = tid + r * 256;
                    ((float4*)sh)[idx] = __ldcg(((const float4*)&src[(size_t)k0 * B]) + idx);
                }
                __syncthreads();
                const float2* wp = wseg + (size_t)k0 * G + n;
#pragma unroll 16
                for (int kk = 0; kk < 128; kk++) {
                    ull w2 = *(const ull*)(wp + (size_t)kk * G);
                    ulonglong2 a = *(const ulonglong2*)&sh[kk * B + b0];
                    acc01 = fma2(w2, a.x, acc01);
                    acc23 = fma2(w2, a.y, acc23);
                }
            }
        }
        __syncthreads();
        {
            float a0, a1, a2, a3;
            unpack2(acc01, a0, a1);
            unpack2(acc23, a2, a3);
            sg[(b0 + 0) * 17 + c] = a0;
            sg[(b0 + 1) * 17 + c] = a1;
            sg[(b0 + 2) * 17 + c] = a2;
            sg[(b0 + 3) * 17 + c] = a3;
        }
        __syncthreads();
        {
            float gi = sg[up_b * 17 + 0 + up_uu];
            float gf = sg[up_b * 17 + 4 + up_uu];
            float gg = sg[up_b * 17 + 8 + up_uu];
            float go = sg[up_b * 17 + 12 + up_uu];
            float cc = sigm(gf) * g_c1[up_idx] + sigm(gi) * tanh_f(gg);
            g_c1[up_idx] = cc;
            float h = sigm(go) * tanh_f(cc);
            g_h1[nxt][up_idx] = h;
            g_h1buf[(size_t)t * H * B + up_idx] = h;
        }
        grid_sync(2 * t + 2);
    }
}

// ---------------- out: out[b][t][o] = blin[o] + sum_k h1buf[t][k][b] * WlinT[k][o] ----------------
__global__ __launch_bounds__(256) void out_kernel(const float* __restrict__ blin,
                                                  float* __restrict__ out) {
    int t = blockIdx.y;
    int o0 = blockIdx.x * 64;
    int tid = threadIdx.x;
    int w = tid >> 5, l = tid & 31;

    __shared__ float sh[64 * 64];   // [k][b]
    float acc0[8], acc1[8];
#pragma unroll
    for (int i = 0; i < 8; i++) { acc0[i] = 0.0f; acc1[i] = 0.0f; }

    for (int k0 = 0; k0 < H; k0 += 64) {
        __syncthreads();
#pragma unroll
        for (int r = 0; r < 4; r++) {
            int idx = tid + r * 256;   // float4 index into 64x64 tile
            ((float4*)sh)[idx] =
                *(((const float4*)&g_h1buf[((size_t)t * H + k0) * B]) + idx);
        }
        __syncthreads();
#pragma unroll 8
        for (int kk = 0; kk < 64; kk++) {
            const float* wr = &g_WlinT[(size_t)(k0 + kk) * DOUT + o0];
            float wa = wr[l];
            float wb = wr[32 + l];
            float a = sh[kk * 64 + w * 8];
#pragma unroll
            for (int i = 0; i < 8; i++) {
                float av = sh[kk * 64 + w * 8 + i];
                acc0[i] += wa * av;
                acc1[i] += wb * av;
            }
            (void)a;
        }
    }
    float ba = blin[o0 + l], bb = blin[o0 + 32 + l];
#pragma unroll
    for (int i = 0; i < 8; i++) {
        int b = w * 8 + i;
        size_t base = ((size_t)b * T + t) * DOUT + o0;
        out[base + l] = acc0[i] + ba;
        out[base + 32 + l] = acc1[i] + bb;
    }
}

// ---------------- launch ----------------
extern "C" void kernel_launch(void* const* d_in, const int* in_sizes, int n_in,
                              void* d_out, int out_size) {
    const float* z    = (const float*)d_in[0];
    const float* x    = (const float*)d_in[1];
    const float* Wih0 = (const float*)d_in[2];
    const float* Whh0 = (const float*)d_in[3];
    const float* bih0 = (const float*)d_in[4];
    const float* bhh0 = (const float*)d_in[5];
    const float* Wih1 = (const float*)d_in[6];
    const float* Whh1 = (const float*)d_in[7];
    const float* bih1 = (const float*)d_in[8];
    const float* bhh1 = (const float*)d_in[9];
    const float* Wlin = (const float*)d_in[10];
    const float* blin = (const float*)d_in[11];
    float* out = (float*)d_out;

    prep_kernel<<<512, 256>>>(z, Wih0, Whh0, bih0, bhh0, Wih1, Whh1, bih1, bhh1, Wlin);
    xproj_kernel<<<dim3(G / 64, T), 256>>>(x);
    recur_kernel<<<NBLK, 256>>>();
    out_kernel<<<dim3(DOUT / 64, T), 256>>>(blin, out);
}

// round 4
// speedup vs baseline: 4.7813x; 4.7813x over previous
#include <cuda_runtime.h>

#define B    64
#define T    512
#define DIN  256
#define H    1024
#define G    4096   // 4*H
#define DOUT 256
#define NBLK 256
#define THR  128
#define CK   128    // k-chunk size

typedef unsigned long long ull;

// ---------------- device scratch ----------------
__device__ float g_Wih0T[(size_t)DIN * G];          // [k][n] for xproj
__device__ float g_Wp0[(size_t)H * NBLK * 16];      // layer0 weights repacked [k][blk][c]
__device__ float g_Wp1[(size_t)2 * H * NBLK * 16];  // layer1 weights repacked [k][blk][c]
__device__ float g_WlinT[(size_t)H * DOUT];         // [k][o]
__device__ float g_b0[G];
__device__ float g_b1[G];
__device__ float g_xp[(size_t)T * G * B];           // [t][n][b]
__device__ float g_h0[2][H * B];                    // [u][b] ping-pong
__device__ float g_h1[2][H * B];
__device__ float g_c0[H * B];
__device__ float g_c1[H * B];
__device__ float g_h1buf[(size_t)T * H * B];        // [t][k][b]

__device__ volatile unsigned g_bar_gen;
__device__ unsigned g_bar_cnt;

// ---------------- helpers ----------------
__device__ __forceinline__ float sigm(float x) { return 1.0f / (1.0f + __expf(-x)); }
__device__ __forceinline__ float tanh_f(float x) {
    float e = __expf(-2.0f * fabsf(x));
    float t = (1.0f - e) / (1.0f + e);
    return x >= 0.0f ? t : -t;
}
__device__ __forceinline__ ull pack2(float lo, float hi) {
    ull r; asm("mov.b64 %0, {%1, %2};" : "=l"(r) : "f"(lo), "f"(hi)); return r;
}
__device__ __forceinline__ void unpack2(ull v, float& lo, float& hi) {
    asm("mov.b64 {%0, %1}, %2;" : "=f"(lo), "=f"(hi) : "l"(v));
}
__device__ __forceinline__ ull fma2(ull a, ull b, ull c) {
    ull d; asm("fma.rn.f32x2 %0, %1, %2, %3;" : "=l"(d) : "l"(a), "l"(b), "l"(c)); return d;
}
__device__ __forceinline__ void cp16(unsigned s, const void* g) {
    asm volatile("cp.async.cg.shared.global [%0], [%1], 16;\n" :: "r"(s), "l"(g));
}
__device__ __forceinline__ void cp_commit() { asm volatile("cp.async.commit_group;\n"); }
template <int N>
__device__ __forceinline__ void cp_wait() { asm volatile("cp.async.wait_group %0;\n" :: "n"(N)); }

// ---------------- prep: repack weights, fold biases, init state ----------------
__global__ void prep_kernel(const float* __restrict__ z,
                            const float* __restrict__ Wih0, const float* __restrict__ Whh0,
                            const float* __restrict__ bih0, const float* __restrict__ bhh0,
                            const float* __restrict__ Wih1, const float* __restrict__ Whh1,
                            const float* __restrict__ bih1, const float* __restrict__ bhh1,
                            const float* __restrict__ Wlin) {
    size_t stride = (size_t)gridDim.x * blockDim.x;
    size_t tid = (size_t)blockIdx.x * blockDim.x + threadIdx.x;
    if (tid == 0) { g_bar_gen = 0; g_bar_cnt = 0; }

    for (size_t i = tid; i < (size_t)DIN * G; i += stride) {
        size_t k = i / G, n = i % G;
        g_Wih0T[i] = Wih0[n * DIN + k];
    }
    // layer0 repack: index = (k*NBLK + blk)*16 + c ; n = (c>>2)*H + blk*4 + (c&3)
    for (size_t i = tid; i < (size_t)H * NBLK * 16; i += stride) {
        size_t k = i / (NBLK * 16);
        size_t rem = i % (NBLK * 16);
        size_t blk = rem >> 4;
        size_t c = rem & 15;
        size_t n = (c >> 2) * H + blk * 4 + (c & 3);
        g_Wp0[i] = Whh0[n * H + k];
    }
    // layer1 repack: k in [0,2H)
    for (size_t i = tid; i < (size_t)2 * H * NBLK * 16; i += stride) {
        size_t k = i / (NBLK * 16);
        size_t rem = i % (NBLK * 16);
        size_t blk = rem >> 4;
        size_t c = rem & 15;
        size_t n = (c >> 2) * H + blk * 4 + (c & 3);
        g_Wp1[i] = (k < H) ? Wih1[n * H + k] : Whh1[n * H + (k - H)];
    }
    for (size_t i = tid; i < (size_t)H * DOUT; i += stride) {
        size_t k = i / DOUT, o = i % DOUT;
        g_WlinT[i] = Wlin[o * H + k];
    }
    for (size_t i = tid; i < G; i += stride) {
        g_b0[i] = bih0[i] + bhh0[i];
        g_b1[i] = bih1[i] + bhh1[i];
    }
    for (size_t i = tid; i < H * B; i += stride) {
        size_t u = i >> 6, b = i & 63;
        float zv = z[b * H + u];
        g_h0[0][i] = zv;
        g_h1[0][i] = zv;
        g_c0[i] = 0.0f;
        g_c1[i] = 0.0f;
    }
}

// ---------------- xproj: g_xp[t][n][b] = b0[n] + x[b][t-1][:] . Wih0T[:][n] ----------------
__global__ __launch_bounds__(256) void xproj_kernel(const float* __restrict__ x) {
    int t = blockIdx.y;
    int n0 = blockIdx.x * 64;
    int tid = threadIdx.x;
    int w = tid >> 5, l = tid & 31;

    __shared__ float sh[64][64];
    float acc0[8], acc1[8];
#pragma unroll
    for (int i = 0; i < 8; i++) { acc0[i] = 0.0f; acc1[i] = 0.0f; }

    if (t > 0) {
        for (int k0 = 0; k0 < DIN; k0 += 64) {
            __syncthreads();
#pragma unroll
            for (int r = 0; r < 4; r++) {
                int v = tid + 256 * r;
                int b = v >> 4, kq = v & 15;
                *(float4*)&sh[b][kq * 4] =
                    *(const float4*)&x[((size_t)b * T + (t - 1)) * DIN + k0 + kq * 4];
            }
            __syncthreads();
#pragma unroll 8
            for (int kk = 0; kk < 64; kk++) {
                const float* wr = &g_Wih0T[(size_t)(k0 + kk) * G + n0];
                float wa = wr[l];
                float wb = wr[32 + l];
#pragma unroll
                for (int i = 0; i < 8; i++) {
                    float a = sh[w * 8 + i][kk];
                    acc0[i] += wa * a;
                    acc1[i] += wb * a;
                }
            }
        }
    }
    float ba = g_b0[n0 + l], bb = g_b0[n0 + 32 + l];
#pragma unroll
    for (int i = 0; i < 8; i++) { acc0[i] += ba; acc1[i] += bb; }
    float4 v;
    size_t basea = ((size_t)t * G + n0 + l) * B + w * 8;
    v = make_float4(acc0[0], acc0[1], acc0[2], acc0[3]); *(float4*)&g_xp[basea] = v;
    v = make_float4(acc0[4], acc0[5], acc0[6], acc0[7]); *(float4*)&g_xp[basea + 4] = v;
    size_t baseb = ((size_t)t * G + n0 + 32 + l) * B + w * 8;
    v = make_float4(acc1[0], acc1[1], acc1[2], acc1[3]); *(float4*)&g_xp[baseb] = v;
    v = make_float4(acc1[4], acc1[5], acc1[6], acc1[7]); *(float4*)&g_xp[baseb + 4] = v;
}

// ---------------- persistent recurrent kernel ----------------
__device__ __forceinline__ void grid_sync(unsigned target) {
    __syncthreads();
    if (threadIdx.x == 0) {
        __threadfence();
        if (atomicAdd(&g_bar_cnt, 1u) == NBLK - 1) {
            g_bar_cnt = 0;
            __threadfence();
            g_bar_gen = target;
        } else {
            while (g_bar_gen < target) {}
            __threadfence();
        }
    }
    __syncthreads();
}

// load one chunk: act CK*B floats (16 x 16B per thread), weights CK rows x 64B (4 x 16B per thread)
__device__ __forceinline__ void load_chunk(unsigned act_a, unsigned w_a, int buf,
                                           const float* __restrict__ actsrc,
                                           const float* __restrict__ wsrc, int tid) {
    const float4* as = (const float4*)actsrc;
    unsigned ab = act_a + (unsigned)buf * CK * B * 4;
#pragma unroll
    for (int i = 0; i < 16; i++) {
        int idx = tid + i * THR;
        cp16(ab + idx * 16, as + idx);
    }
    const float* wr = wsrc + (size_t)tid * NBLK * 16;
    unsigned wb = w_a + (unsigned)buf * CK * 16 * 4 + (unsigned)tid * 64;
#pragma unroll
    for (int j = 0; j < 4; j++)
        cp16(wb + j * 16, wr + j * 4);
}

__device__ __forceinline__ void compute_chunk(const float* __restrict__ act_s,
                                              const float* __restrict__ w_s,
                                              int c, int b0,
                                              ull& a0, ull& a1, ull& a2, ull& a3) {
#pragma unroll 8
    for (int kk = 0; kk < CK; kk++) {
        float w = w_s[kk * 16 + c];
        ull w2 = pack2(w, w);
        const ulonglong2* ap = (const ulonglong2*)&act_s[kk * B + b0];
        ulonglong2 x0 = ap[0];
        ulonglong2 x1 = ap[1];
        a0 = fma2(w2, x0.x, a0);
        a1 = fma2(w2, x0.y, a1);
        a2 = fma2(w2, x1.x, a2);
        a3 = fma2(w2, x1.y, a3);
    }
}

#define SMEM_FLOATS (2 * CK * B + 2 * CK * 16 + 64 * 17)

__global__ void __launch_bounds__(THR, 2) recur_kernel() {
    extern __shared__ float smem[];
    float* act_s = smem;                       // 2 * CK*B
    float* w_s   = smem + 2 * CK * B;          // 2 * CK*16
    float* sg    = w_s + 2 * CK * 16;          // 64*17

    unsigned sb = (unsigned)__cvta_generic_to_shared(smem);
    unsigned act_a = sb;
    unsigned w_a = sb + 2 * CK * B * 4;

    int tid = threadIdx.x;
    int blk = blockIdx.x;
    int c = tid & 15;          // col: gate = c>>2, uu = c&3
    int bg = tid >> 4;         // 0..7
    int b0 = bg * 8;
    int u0 = blk * 4;
    int n = (c >> 2) * H + u0 + (c & 3);
    const float bv1 = g_b1[n];

    for (int t = 0; t < T; t++) {
        int cur = t & 1, nxt = cur ^ 1;

        // ================= layer 0 =================
        ull a0, a1, a2, a3;
        {
            const float4* xq = (const float4*)&g_xp[((size_t)t * G + n) * B + b0];
            float4 xa = xq[0], xb = xq[1];
            a0 = pack2(xa.x, xa.y);
            a1 = pack2(xa.z, xa.w);
            a2 = pack2(xb.x, xb.y);
            a3 = pack2(xb.z, xb.w);
        }
        {
            const float* hsrc = g_h0[cur];
            load_chunk(act_a, w_a, 0, hsrc, &g_Wp0[(size_t)blk * 16], tid);
            cp_commit();
            int buf = 0;
            for (int ch = 0; ch < 8; ch++) {
                if (ch + 1 < 8) {
                    load_chunk(act_a, w_a, buf ^ 1, hsrc + (size_t)(ch + 1) * CK * B,
                               &g_Wp0[((size_t)(ch + 1) * CK * NBLK + blk) * 16], tid);
                    cp_commit();
                    cp_wait<1>();
                } else {
                    cp_wait<0>();
                }
                __syncthreads();
                compute_chunk(act_s + buf * CK * B, w_s + buf * CK * 16, c, b0, a0, a1, a2, a3);
                __syncthreads();
                buf ^= 1;
            }
        }
        {
            float v0, v1, v2, v3, v4, v5, v6, v7;
            unpack2(a0, v0, v1); unpack2(a1, v2, v3);
            unpack2(a2, v4, v5); unpack2(a3, v6, v7);
            sg[(b0 + 0) * 17 + c] = v0;
            sg[(b0 + 1) * 17 + c] = v1;
            sg[(b0 + 2) * 17 + c] = v2;
            sg[(b0 + 3) * 17 + c] = v3;
            sg[(b0 + 4) * 17 + c] = v4;
            sg[(b0 + 5) * 17 + c] = v5;
            sg[(b0 + 6) * 17 + c] = v6;
            sg[(b0 + 7) * 17 + c] = v7;
        }
        __syncthreads();
#pragma unroll
        for (int j = 0; j < 2; j++) {
            int item = tid + j * THR;
            int uu = item >> 6, b = item & 63;
            int idx = (u0 + uu) * B + b;
            float gi = sg[b * 17 + 0 + uu];
            float gf = sg[b * 17 + 4 + uu];
            float gg = sg[b * 17 + 8 + uu];
            float go = sg[b * 17 + 12 + uu];
            float cc = sigm(gf) * g_c0[idx] + sigm(gi) * tanh_f(gg);
            g_c0[idx] = cc;
            g_h0[nxt][idx] = sigm(go) * tanh_f(cc);
        }
        grid_sync(2 * t + 1);

        // ================= layer 1 =================
        a0 = pack2(bv1, bv1);
        a1 = a0; a2 = a0; a3 = a0;
        {
            const float* h0n = g_h0[nxt];
            const float* h1o = g_h1[cur];
            load_chunk(act_a, w_a, 0, h0n, &g_Wp1[(size_t)blk * 16], tid);
            cp_commit();
            int buf = 0;
            for (int ch = 0; ch < 16; ch++) {
                if (ch + 1 < 16) {
                    int nc = ch + 1;
                    const float* src = (nc < 8) ? (h0n + (size_t)nc * CK * B)
                                                : (h1o + (size_t)(nc - 8) * CK * B);
                    load_chunk(act_a, w_a, buf ^ 1, src,
                               &g_Wp1[((size_t)nc * CK * NBLK + blk) * 16], tid);
                    cp_commit();
                    cp_wait<1>();
                } else {
                    cp_wait<0>();
                }
                __syncthreads();
                compute_chunk(act_s + buf * CK * B, w_s + buf * CK * 16, c, b0, a0, a1, a2, a3);
                __syncthreads();
                buf ^= 1;
            }
        }
        {
            float v0, v1, v2, v3, v4, v5, v6, v7;
            unpack2(a0, v0, v1); unpack2(a1, v2, v3);
            unpack2(a2, v4, v5); unpack2(a3, v6, v7);
            sg[(b0 + 0) * 17 + c] = v0;
            sg[(b0 + 1) * 17 + c] = v1;
            sg[(b0 + 2) * 17 + c] = v2;
            sg[(b0 + 3) * 17 + c] = v3;
            sg[(b0 + 4) * 17 + c] = v4;
            sg[(b0 + 5) * 17 + c] = v5;
            sg[(b0 + 6) * 17 + c] = v6;
            sg[(b0 + 7) * 17 + c] = v7;
        }
        __syncthreads();
#pragma unroll
        for (int j = 0; j < 2; j++) {
            int item = tid + j * THR;
            int uu = item >> 6, b = item & 63;
            int idx = (u0 + uu) * B + b;
            float gi = sg[b * 17 + 0 + uu];
            float gf = sg[b * 17 + 4 + uu];
            float gg = sg[b * 17 + 8 + uu];
            float go = sg[b * 17 + 12 + uu];
            float cc = sigm(gf) * g_c1[idx] + sigm(gi) * tanh_f(gg);
            g_c1[idx] = cc;
            float h = sigm(go) * tanh_f(cc);
            g_h1[nxt][idx] = h;
            g_h1buf[(size_t)t * H * B + idx] = h;
        }
        grid_sync(2 * t + 2);
    }
}

// ---------------- out: out[b][t][o] = blin[o] + sum_k h1buf[t][k][b] * WlinT[k][o] ----------------
__global__ __launch_bounds__(256) void out_kernel(const float* __restrict__ blin,
                                                  float* __restrict__ out) {
    int t = blockIdx.y;
    int o0 = blockIdx.x * 64;
    int tid = threadIdx.x;
    int w = tid >> 5, l = tid & 31;

    __shared__ float sh[64 * 64];   // [k][b]
    float acc0[8], acc1[8];
#pragma unroll
    for (int i = 0; i < 8; i++) { acc0[i] = 0.0f; acc1[i] = 0.0f; }

    for (int k0 = 0; k0 < H; k0 += 64) {
        __syncthreads();
#pragma unroll
        for (int r = 0; r < 4; r++) {
            int idx = tid + r * 256;
            ((float4*)sh)[idx] =
                *(((const float4*)&g_h1buf[((size_t)t * H + k0) * B]) + idx);
        }
        __syncthreads();
#pragma unroll 8
        for (int kk = 0; kk < 64; kk++) {
            const float* wr = &g_WlinT[(size_t)(k0 + kk) * DOUT + o0];
            float wa = wr[l];
            float wb = wr[32 + l];
#pragma unroll
            for (int i = 0; i < 8; i++) {
                float av = sh[kk * 64 + w * 8 + i];
                acc0[i] += wa * av;
                acc1[i] += wb * av;
            }
        }
    }
    float ba = blin[o0 + l], bb = blin[o0 + 32 + l];
#pragma unroll
    for (int i = 0; i < 8; i++) {
        int b = w * 8 + i;
        size_t base = ((size_t)b * T + t) * DOUT + o0;
        out[base + l] = acc0[i] + ba;
        out[base + 32 + l] = acc1[i] + bb;
    }
}

// ---------------- launch ----------------
extern "C" void kernel_launch(void* const* d_in, const int* in_sizes, int n_in,
                              void* d_out, int out_size) {
    const float* z    = (const float*)d_in[0];
    const float* x    = (const float*)d_in[1];
    const float* Wih0 = (const float*)d_in[2];
    const float* Whh0 = (const float*)d_in[3];
    const float* bih0 = (const float*)d_in[4];
    const float* bhh0 = (const float*)d_in[5];
    const float* Wih1 = (const float*)d_in[6];
    const float* Whh1 = (const float*)d_in[7];
    const float* bih1 = (const float*)d_in[8];
    const float* bhh1 = (const float*)d_in[9];
    const float* Wlin = (const float*)d_in[10];
    const float* blin = (const float*)d_in[11];
    float* out = (float*)d_out;

    cudaFuncSetAttribute(recur_kernel, cudaFuncAttributeMaxDynamicSharedMemorySize,
                         SMEM_FLOATS * 4);

    prep_kernel<<<512, 256>>>(z, Wih0, Whh0, bih0, bhh0, Wih1, Whh1, bih1, bhh1, Wlin);
    xproj_kernel<<<dim3(G / 64, T), 256>>>(x);
    recur_kernel<<<NBLK, THR, SMEM_FLOATS * 4>>>();
    out_kernel<<<dim3(DOUT / 64, T), 256>>>(blin, out);
}

// round 6
// speedup vs baseline: 4.9619x; 1.0378x over previous
#include <cuda_runtime.h>

#define B    64
#define T    512
#define DIN  256
#define H    1024
#define G    4096   // 4*H
#define DOUT 256
#define NBLK 128
#define THR  256
#define CK   128    // k-chunk rows

typedef unsigned long long ull;

// SMEM float offsets
#define ACT_OFF  0              // 2 bufs x 8192 floats (32KB each)
#define W_OFF    16384          // 2 bufs x 8192 floats (32KB each)
#define SG_OFF   32768          // 64*33 floats
#define SMEM_BYTES ((32768 + 64 * 33) * 4 + 16)
#define BAR_BYTE_OFF ((32768 + 64 * 33) * 4)

// ---------------- device scratch ----------------
__device__ float g_Wih0T[(size_t)DIN * G];            // [k][n] for xproj
// layer0 weights: [blk][k][p][4] quads (w_c,w_c,w_c16,w_c16), c=p+16*(j>>1)
__device__ float g_Wp0[(size_t)NBLK * H * 64];
// layer1 weights: [blk][k 0..2H)[p][4]
__device__ float g_Wp1[(size_t)NBLK * 2 * H * 64];
__device__ float g_WlinT[(size_t)H * DOUT];           // [k][o]
__device__ float g_b0[G];
__device__ float g_b1[G];
__device__ float g_xp[(size_t)T * G * B];             // [t][n][b]
__device__ float g_h0[2][H * B];                      // [u][b] ping-pong
__device__ float g_h1[2][H * B];
__device__ float g_h1buf[(size_t)T * H * B];          // [t][k][b]

__device__ volatile unsigned g_bar_gen;
__device__ unsigned g_bar_cnt;

// ---------------- helpers ----------------
__device__ __forceinline__ float sigm(float x) { return 1.0f / (1.0f + __expf(-x)); }
__device__ __forceinline__ float tanh_f(float x) {
    float e = __expf(-2.0f * fabsf(x));
    float t = (1.0f - e) / (1.0f + e);
    return x >= 0.0f ? t : -t;
}
__device__ __forceinline__ ull pack2(float lo, float hi) {
    ull r; asm("mov.b64 %0, {%1, %2};" : "=l"(r) : "f"(lo), "f"(hi)); return r;
}
__device__ __forceinline__ void unpack2(ull v, float& lo, float& hi) {
    asm("mov.b64 {%0, %1}, %2;" : "=f"(lo), "=f"(hi) : "l"(v));
}
__device__ __forceinline__ ull fma2(ull a, ull b, ull c) {
    ull d; asm("fma.rn.f32x2 %0, %1, %2, %3;" : "=l"(d) : "l"(a), "l"(b), "l"(c)); return d;
}
__device__ __forceinline__ void mbar_init(unsigned mbar, unsigned cnt) {
    asm volatile("mbarrier.init.shared.b64 [%0], %1;" :: "r"(mbar), "r"(cnt) : "memory");
}
__device__ __forceinline__ void mbar_expect_tx(unsigned mbar, unsigned bytes) {
    asm volatile("mbarrier.arrive.expect_tx.shared.b64 _, [%0], %1;" :: "r"(mbar), "r"(bytes) : "memory");
}
__device__ __forceinline__ void mbar_wait(unsigned mbar, unsigned phase) {
    asm volatile(
        "{\n\t"
        ".reg .pred P;\n\t"
        "WAIT_%=:\n\t"
        "mbarrier.try_wait.parity.acquire.cta.shared::cta.b64 P, [%0], %1, 0x989680;\n\t"
        "@P bra.uni DONE_%=;\n\t"
        "bra.uni WAIT_%=;\n\t"
        "DONE_%=:\n\t"
        "}"
        :: "r"(mbar), "r"(phase) : "memory");
}
__device__ __forceinline__ void bulk_cp(unsigned dst, const void* src, unsigned bytes, unsigned mbar) {
    asm volatile(
        "cp.async.bulk.shared::cluster.global.mbarrier::complete_tx::bytes [%0], [%1], %2, [%3];"
        :: "r"(dst), "l"(src), "r"(bytes), "r"(mbar) : "memory");
}

// ---------------- prep ----------------
__global__ void prep_kernel(const float* __restrict__ z,
                            const float* __restrict__ Wih0, const float* __restrict__ Whh0,
                            const float* __restrict__ bih0, const float* __restrict__ bhh0,
                            const float* __restrict__ Wih1, const float* __restrict__ Whh1,
                            const float* __restrict__ bih1, const float* __restrict__ bhh1,
                            const float* __restrict__ Wlin) {
    size_t stride = (size_t)gridDim.x * blockDim.x;
    size_t tid = (size_t)blockIdx.x * blockDim.x + threadIdx.x;
    if (tid == 0) { g_bar_gen = 0; g_bar_cnt = 0; }

    for (size_t i = tid; i < (size_t)DIN * G; i += stride) {
        size_t k = i / G, n = i % G;
        g_Wih0T[i] = Wih0[n * DIN + k];
    }
    // layer0 quads: i = ((blk*1024 + k)*16 + p)*4 + j
    for (size_t i = tid; i < (size_t)NBLK * H * 64; i += stride) {
        size_t j = i & 3;
        size_t p = (i >> 2) & 15;
        size_t k = (i >> 6) & (H - 1);
        size_t blk = i >> 16;
        size_t c = p + 16 * (j >> 1);
        size_t n = (c >> 3) * H + blk * 8 + (c & 7);
        g_Wp0[i] = Whh0[n * H + k];
    }
    // layer1 quads: k in [0,2H)
    for (size_t i = tid; i < (size_t)NBLK * 2 * H * 64; i += stride) {
        size_t j = i & 3;
        size_t p = (i >> 2) & 15;
        size_t k = (i >> 6) & (2 * H - 1);
        size_t blk = i >> 17;
        size_t c = p + 16 * (j >> 1);
        size_t n = (c >> 3) * H + blk * 8 + (c & 7);
        g_Wp1[i] = (k < H) ? Wih1[n * H + k] : Whh1[n * H + (k - H)];
    }
    for (size_t i = tid; i < (size_t)H * DOUT; i += stride) {
        size_t k = i / DOUT, o = i % DOUT;
        g_WlinT[i] = Wlin[o * H + k];
    }
    for (size_t i = tid; i < G; i += stride) {
        g_b0[i] = bih0[i] + bhh0[i];
        g_b1[i] = bih1[i] + bhh1[i];
    }
    for (size_t i = tid; i < H * B; i += stride) {
        size_t u = i >> 6, b = i & 63;
        float zv = z[b * H + u];
        g_h0[0][i] = zv;
        g_h1[0][i] = zv;
    }
}

// ---------------- xproj: g_xp[t][n][b] = b0[n] + x[b][t-1][:] . Wih0T[:][n] ----------------
__global__ __launch_bounds__(256) void xproj_kernel(const float* __restrict__ x) {
    int t = blockIdx.y;
    int n0 = blockIdx.x * 64;
    int tid = threadIdx.x;
    int w = tid >> 5, l = tid & 31;

    __shared__ float sh[64][64];
    float acc0[8], acc1[8];
#pragma unroll
    for (int i = 0; i < 8; i++) { acc0[i] = 0.0f; acc1[i] = 0.0f; }

    if (t > 0) {
        for (int k0 = 0; k0 < DIN; k0 += 64) {
            __syncthreads();
#pragma unroll
            for (int r = 0; r < 4; r++) {
                int v = tid + 256 * r;
                int b = v >> 4, kq = v & 15;
                *(float4*)&sh[b][kq * 4] =
                    *(const float4*)&x[((size_t)b * T + (t - 1)) * DIN + k0 + kq * 4];
            }
            __syncthreads();
#pragma unroll 8
            for (int kk = 0; kk < 64; kk++) {
                const float* wr = &g_Wih0T[(size_t)(k0 + kk) * G + n0];
                float wa = wr[l];
                float wb = wr[32 + l];
#pragma unroll
                for (int i = 0; i < 8; i++) {
                    float a = sh[w * 8 + i][kk];
                    acc0[i] += wa * a;
                    acc1[i] += wb * a;
                }
            }
        }
    }
    float ba = g_b0[n0 + l], bb = g_b0[n0 + 32 + l];
#pragma unroll
    for (int i = 0; i < 8; i++) { acc0[i] += ba; acc1[i] += bb; }
    float4 v;
    size_t basea = ((size_t)t * G + n0 + l) * B + w * 8;
    v = make_float4(acc0[0], acc0[1], acc0[2], acc0[3]); *(float4*)&g_xp[basea] = v;
    v = make_float4(acc0[4], acc0[5], acc0[6], acc0[7]); *(float4*)&g_xp[basea + 4] = v;
    size_t baseb = ((size_t)t * G + n0 + 32 + l) * B + w * 8;
    v = make_float4(acc1[0], acc1[1], acc1[2], acc1[3]); *(float4*)&g_xp[baseb] = v;
    v = make_float4(acc1[4], acc1[5], acc1[6], acc1[7]); *(float4*)&g_xp[baseb + 4] = v;
}

// ---------------- persistent recurrent kernel ----------------
__device__ __forceinline__ void grid_sync(unsigned target) {
    __syncthreads();
    if (threadIdx.x == 0) {
        __threadfence();
        if (atomicAdd(&g_bar_cnt, 1u) == NBLK - 1) {
            g_bar_cnt = 0;
            __threadfence();
            g_bar_gen = target;
        } else {
            while (g_bar_gen < target) {}
            __threadfence();
        }
    }
    __syncthreads();
}

__device__ __forceinline__ void compute_chunk(const float* __restrict__ act_s,
                                              const float* __restrict__ w_s,
                                              int cl4, int b0,
                                              ull& a0, ull& a1, ull& a2, ull& a3) {
#pragma unroll 16
    for (int kk = 0; kk < CK; kk++) {
        ulonglong2 w2 = *(const ulonglong2*)&w_s[kk * 64 + cl4];   // (wA,wA | wB,wB)
        ulonglong2 x  = *(const ulonglong2*)&act_s[kk * B + b0];   // 4 batches
        a0 = fma2(w2.x, x.x, a0);
        a1 = fma2(w2.x, x.y, a1);
        a2 = fma2(w2.y, x.x, a2);
        a3 = fma2(w2.y, x.y, a3);
    }
}

__global__ void __launch_bounds__(THR, 1) recur_kernel() {
    extern __shared__ float smem[];
    unsigned sb = (unsigned)__cvta_generic_to_shared(smem);
    unsigned bar0 = sb + BAR_BYTE_OFF;
    unsigned bar1 = bar0 + 8;

    int tid = threadIdx.x;
    int blk = blockIdx.x;
    int wrp = tid >> 5, lane = tid & 31;
    // lane mapping: 8 contiguous cols x 4 contiguous batch-groups per warp
    int cl = (lane & 7) | ((wrp & 1) << 3);       // 0..15
    int bg = (lane >> 3) | ((wrp >> 1) << 2);     // 0..15
    int cl4 = cl * 4;
    int b0 = bg * 4;
    int u0 = blk * 8;
    int cA = cl, cB = cl + 16;
    int nA = (cA >> 3) * H + u0 + (cA & 7);
    int nB = (cB >> 3) * H + u0 + (cB & 7);

    float* sg = smem + SG_OFF;

    if (tid == 0) {
        mbar_init(bar0, 1);
        mbar_init(bar1, 1);
        asm volatile("fence.proxy.async.shared::cta;" ::: "memory");
    }
    __syncthreads();

    unsigned ph0 = 0, ph1 = 0;
    const float bvA = g_b1[nA];
    const float bvB = g_b1[nB];

    // register-resident cell states (block-private)
    float c0r[2] = {0.0f, 0.0f};
    float c1r[2] = {0.0f, 0.0f};

    const float* w0base = &g_Wp0[(size_t)blk * H * 64];
    const float* w1base = &g_Wp1[(size_t)blk * 2 * H * 64];

    for (int t = 0; t < T; t++) {
        int cur = t & 1, nxt = cur ^ 1;
        const float* h0cur = g_h0[cur];

        // ================= layer 0 (8 chunks) =================
        if (tid == 0) {
            mbar_expect_tx(bar0, 65536u);
            bulk_cp(sb + ACT_OFF * 4, h0cur, 32768u, bar0);
            bulk_cp(sb + W_OFF * 4, w0base, 32768u, bar0);
        }
        ull a0, a1, a2, a3;
        {
            const float4* xa = (const float4*)&g_xp[((size_t)t * G + nA) * B + b0];
            const float4* xb = (const float4*)&g_xp[((size_t)t * G + nB) * B + b0];
            float4 va = *xa, vb = *xb;
            a0 = pack2(va.x, va.y);
            a1 = pack2(va.z, va.w);
            a2 = pack2(vb.x, vb.y);
            a3 = pack2(vb.z, vb.w);
        }
        for (int ch = 0; ch < 8; ch++) {
            int buf = ch & 1;
            if (tid == 0 && ch + 1 < 8) {
                unsigned bb = buf ? bar0 : bar1;
                int nb = buf ^ 1;
                mbar_expect_tx(bb, 65536u);
                bulk_cp(sb + (ACT_OFF + nb * 8192) * 4, h0cur + (size_t)(ch + 1) * CK * B, 32768u, bb);
                bulk_cp(sb + (W_OFF + nb * 8192) * 4, w0base + (size_t)(ch + 1) * CK * 64, 32768u, bb);
            }
            if (buf == 0) { mbar_wait(bar0, ph0); ph0 ^= 1; }
            else          { mbar_wait(bar1, ph1); ph1 ^= 1; }
            compute_chunk(smem + ACT_OFF + buf * 8192, smem + W_OFF + buf * 8192,
                          cl4, b0, a0, a1, a2, a3);
            __syncthreads();
        }
        {
            float v0, v1, v2, v3, u0_, u1_, u2_, u3_;
            unpack2(a0, v0, v1); unpack2(a1, v2, v3);
            unpack2(a2, u0_, u1_); unpack2(a3, u2_, u3_);
            sg[(b0 + 0) * 33 + cl] = v0;
            sg[(b0 + 1) * 33 + cl] = v1;
            sg[(b0 + 2) * 33 + cl] = v2;
            sg[(b0 + 3) * 33 + cl] = v3;
            sg[(b0 + 0) * 33 + cl + 16] = u0_;
            sg[(b0 + 1) * 33 + cl + 16] = u1_;
            sg[(b0 + 2) * 33 + cl + 16] = u2_;
            sg[(b0 + 3) * 33 + cl + 16] = u3_;
        }
        __syncthreads();
#pragma unroll
        for (int j = 0; j < 2; j++) {
            int item = tid + j * THR;
            int uu = item >> 6, b = item & 63;
            float gi = sg[b * 33 + 0 + uu];
            float gf = sg[b * 33 + 8 + uu];
            float gg = sg[b * 33 + 16 + uu];
            float go = sg[b * 33 + 24 + uu];
            float cc = sigm(gf) * c0r[j] + sigm(gi) * tanh_f(gg);
            c0r[j] = cc;
            g_h0[nxt][(u0 + uu) * B + b] = sigm(go) * tanh_f(cc);
        }
        grid_sync(2 * t + 1);

        // ================= layer 1 (16 chunks) =================
        const float* h0n = g_h0[nxt];
        const float* h1o = g_h1[cur];
        if (tid == 0) {
            mbar_expect_tx(bar0, 65536u);
            bulk_cp(sb + ACT_OFF * 4, h0n, 32768u, bar0);
            bulk_cp(sb + W_OFF * 4, w1base, 32768u, bar0);
        }
        a0 = pack2(bvA, bvA);
        a1 = a0;
        a2 = pack2(bvB, bvB);
        a3 = a2;
        for (int ch = 0; ch < 16; ch++) {
            int buf = ch & 1;
            if (tid == 0 && ch + 1 < 16) {
                unsigned bb = buf ? bar0 : bar1;
                int nb = buf ^ 1;
                int nc = ch + 1;
                const float* src = (nc < 8) ? (h0n + (size_t)nc * CK * B)
                                            : (h1o + (size_t)(nc - 8) * CK * B);
                mbar_expect_tx(bb, 65536u);
                bulk_cp(sb + (ACT_OFF + nb * 8192) * 4, src, 32768u, bb);
                bulk_cp(sb + (W_OFF + nb * 8192) * 4, w1base + (size_t)nc * CK * 64, 32768u, bb);
            }
            if (buf == 0) { mbar_wait(bar0, ph0); ph0 ^= 1; }
            else          { mbar_wait(bar1, ph1); ph1 ^= 1; }
            compute_chunk(smem + ACT_OFF + buf * 8192, smem + W_OFF + buf * 8192,
                          cl4, b0, a0, a1, a2, a3);
            __syncthreads();
        }
        {
            float v0, v1, v2, v3, u0_, u1_, u2_, u3_;
            unpack2(a0, v0, v1); unpack2(a1, v2, v3);
            unpack2(a2, u0_, u1_); unpack2(a3, u2_, u3_);
            sg[(b0 + 0) * 33 + cl] = v0;
            sg[(b0 + 1) * 33 + cl] = v1;
            sg[(b0 + 2) * 33 + cl] = v2;
            sg[(b0 + 3) * 33 + cl] = v3;
            sg[(b0 + 0) * 33 + cl + 16] = u0_;
            sg[(b0 + 1) * 33 + cl + 16] = u1_;
            sg[(b0 + 2) * 33 + cl + 16] = u2_;
            sg[(b0 + 3) * 33 + cl + 16] = u3_;
        }
        __syncthreads();
#pragma unroll
        for (int j = 0; j < 2; j++) {
            int item = tid + j * THR;
            int uu = item >> 6, b = item & 63;
            float gi = sg[b * 33 + 0 + uu];
            float gf = sg[b * 33 + 8 + uu];
            float gg = sg[b * 33 + 16 + uu];
            float go = sg[b * 33 + 24 + uu];
            float cc = sigm(gf) * c1r[j] + sigm(gi) * tanh_f(gg);
            c1r[j] = cc;
            float h = sigm(go) * tanh_f(cc);
            int idx = (u0 + uu) * B + b;
            g_h1[nxt][idx] = h;
            g_h1buf[(size_t)t * H * B + idx] = h;
        }
        grid_sync(2 * t + 2);
    }
}

// ---------------- out: out[b][t][o] = blin[o] + sum_k h1buf[t][k][b] * WlinT[k][o] ----------------
__global__ __launch_bounds__(256) void out_kernel(const float* __restrict__ blin,
                                                  float* __restrict__ out) {
    int t = blockIdx.y;
    int o0 = blockIdx.x * 64;
    int tid = threadIdx.x;
    int w = tid >> 5, l = tid & 31;

    __shared__ float sh[64 * 64];   // [k][b]
    float acc0[8], acc1[8];
#pragma unroll
    for (int i = 0; i < 8; i++) { acc0[i] = 0.0f; acc1[i] = 0.0f; }

    for (int k0 = 0; k0 < H; k0 += 64) {
        __syncthreads();
#pragma unroll
        for (int r = 0; r < 4; r++) {
            int idx = tid + r * 256;
            ((float4*)sh)[idx] =
                *(((const float4*)&g_h1buf[((size_t)t * H + k0) * B]) + idx);
        }
        __syncthreads();
#pragma unroll 8
        for (int kk = 0; kk < 64; kk++) {
            const float* wr = &g_WlinT[(size_t)(k0 + kk) * DOUT + o0];
            float wa = wr[l];
            float wb = wr[32 + l];
#pragma unroll
            for (int i = 0; i < 8; i++) {
                float av = sh[kk * 64 + w * 8 + i];
                acc0[i] += wa * av;
                acc1[i] += wb * av;
            }
        }
    }
    float ba = blin[o0 + l], bb = blin[o0 + 32 + l];
#pragma unroll
    for (int i = 0; i < 8; i++) {
        int b = w * 8 + i;
        size_t base = ((size_t)b * T + t) * DOUT + o0;
        out[base + l] = acc0[i] + ba;
        out[base + 32 + l] = acc1[i] + bb;
    }
}

// ---------------- launch ----------------
extern "C" void kernel_launch(void* const* d_in, const int* in_sizes, int n_in,
                              void* d_out, int out_size) {
    const float* z    = (const float*)d_in[0];
    const float* x    = (const float*)d_in[1];
    const float* Wih0 = (const float*)d_in[2];
    const float* Whh0 = (const float*)d_in[3];
    const float* bih0 = (const float*)d_in[4];
    const float* bhh0 = (const float*)d_in[5];
    const float* Wih1 = (const float*)d_in[6];
    const float* Whh1 = (const float*)d_in[7];
    const float* bih1 = (const float*)d_in[8];
    const float* bhh1 = (const float*)d_in[9];
    const float* Wlin = (const float*)d_in[10];
    const float* blin = (const float*)d_in[11];
    float* out = (float*)d_out;

    cudaFuncSetAttribute(recur_kernel, cudaFuncAttributeMaxDynamicSharedMemorySize,
                         SMEM_BYTES);

    prep_kernel<<<512, 256>>>(z, Wih0, Whh0, bih0, bhh0, Wih1, Whh1, bih1, bhh1, Wlin);
    xproj_kernel<<<dim3(G / 64, T), 256>>>(x);
    recur_kernel<<<NBLK, THR, SMEM_BYTES>>>();
    out_kernel<<<dim3(DOUT / 64, T), 256>>>(blin, out);
}

// round 7
// speedup vs baseline: 9.5042x; 1.9154x over previous
#include <cuda_runtime.h>

#define B    64
#define T    512
#define DIN  256
#define H    1024
#define G    4096   // 4*H
#define DOUT 256
#define NBLK 128
#define THR  256

typedef unsigned long long ull;

// SMEM float offsets
#define ACT_OFF   0            // 2 bufs x 8192 floats (32KB each)
#define WT_OFF    16384        // 2 bufs x 4096 floats (16KB each)
#define PART_OFF  24576        // 16384 floats (64KB)
#define SMEM_FLOATS (24576 + 16384)
#define BAR_BYTE_OFF (SMEM_FLOATS * 4)
#define SMEM_BYTES (BAR_BYTE_OFF + 16)

// ---------------- device scratch ----------------
__device__ float g_Wih0T[(size_t)DIN * G];        // [k][n] for xproj
__device__ float g_Wq0[(size_t)NBLK * H * 32];    // layer0: [blk][k][c]  c=gate*8+unit
__device__ float g_Wq1[(size_t)NBLK * 2 * H * 32];// layer1: [blk][k(0..2H)][c]
__device__ float g_WlinT[(size_t)H * DOUT];       // [k][o]
__device__ float g_b0[G];
__device__ float g_b1[G];
__device__ float g_xp[(size_t)T * G * B];         // [t][n][b]
__device__ float g_h0[2][H * B];                  // [u][b] ping-pong
__device__ float g_h1[2][H * B];
__device__ float g_h1buf[(size_t)T * H * B];      // [t][k][b]

__device__ volatile unsigned g_bar_gen;
__device__ unsigned g_bar_cnt;

// ---------------- helpers ----------------
__device__ __forceinline__ float sigm(float x) { return 1.0f / (1.0f + __expf(-x)); }
__device__ __forceinline__ float tanh_f(float x) {
    float e = __expf(-2.0f * fabsf(x));
    float t = (1.0f - e) / (1.0f + e);
    return x >= 0.0f ? t : -t;
}
__device__ __forceinline__ ull pack2(float lo, float hi) {
    ull r; asm("mov.b64 %0, {%1, %2};" : "=l"(r) : "f"(lo), "f"(hi)); return r;
}
__device__ __forceinline__ void unpack2(ull v, float& lo, float& hi) {
    asm("mov.b64 {%0, %1}, %2;" : "=f"(lo), "=f"(hi) : "l"(v));
}
__device__ __forceinline__ ull fma2(ull a, ull b, ull c) {
    ull d; asm("fma.rn.f32x2 %0, %1, %2, %3;" : "=l"(d) : "l"(a), "l"(b), "l"(c)); return d;
}
__device__ __forceinline__ void mbar_init(unsigned mbar, unsigned cnt) {
    asm volatile("mbarrier.init.shared.b64 [%0], %1;" :: "r"(mbar), "r"(cnt) : "memory");
}
__device__ __forceinline__ void mbar_expect_tx(unsigned mbar, unsigned bytes) {
    asm volatile("mbarrier.arrive.expect_tx.shared.b64 _, [%0], %1;" :: "r"(mbar), "r"(bytes) : "memory");
}
__device__ __forceinline__ void mbar_wait(unsigned mbar, unsigned phase) {
    asm volatile(
        "{\n\t"
        ".reg .pred P;\n\t"
        "WAIT_%=:\n\t"
        "mbarrier.try_wait.parity.acquire.cta.shared::cta.b64 P, [%0], %1, 0x989680;\n\t"
        "@P bra.uni DONE_%=;\n\t"
        "bra.uni WAIT_%=;\n\t"
        "DONE_%=:\n\t"
        "}"
        :: "r"(mbar), "r"(phase) : "memory");
}
__device__ __forceinline__ void bulk_cp(unsigned dst, const void* src, unsigned bytes, unsigned mbar) {
    asm volatile(
        "cp.async.bulk.shared::cluster.global.mbarrier::complete_tx::bytes [%0], [%1], %2, [%3];"
        :: "r"(dst), "l"(src), "r"(bytes), "r"(mbar) : "memory");
}

// ---------------- prep ----------------
__global__ void prep_kernel(const float* __restrict__ z,
                            const float* __restrict__ Wih0, const float* __restrict__ Whh0,
                            const float* __restrict__ bih0, const float* __restrict__ bhh0,
                            const float* __restrict__ Wih1, const float* __restrict__ Whh1,
                            const float* __restrict__ bih1, const float* __restrict__ bhh1,
                            const float* __restrict__ Wlin) {
    size_t stride = (size_t)gridDim.x * blockDim.x;
    size_t tid = (size_t)blockIdx.x * blockDim.x + threadIdx.x;
    if (tid == 0) { g_bar_gen = 0; g_bar_cnt = 0; }

    for (size_t i = tid; i < (size_t)DIN * G; i += stride) {
        size_t k = i / G, n = i % G;
        g_Wih0T[i] = Wih0[n * DIN + k];
    }
    // layer0: i = (blk*1024 + k)*32 + c ; c = gate*8 + unit; n = gate*H + blk*8 + unit
    for (size_t i = tid; i < (size_t)NBLK * H * 32; i += stride) {
        size_t c = i & 31;
        size_t k = (i >> 5) & (H - 1);
        size_t blk = i >> 15;
        size_t n = (c >> 3) * H + blk * 8 + (c & 7);
        g_Wq0[i] = Whh0[n * H + k];
    }
    // layer1: i = (blk*2048 + k)*32 + c, k in [0,2H)
    for (size_t i = tid; i < (size_t)NBLK * 2 * H * 32; i += stride) {
        size_t c = i & 31;
        size_t k = (i >> 5) & (2 * H - 1);
        size_t blk = i >> 16;
        size_t n = (c >> 3) * H + blk * 8 + (c & 7);
        g_Wq1[i] = (k < H) ? Wih1[n * H + k] : Whh1[n * H + (k - H)];
    }
    for (size_t i = tid; i < (size_t)H * DOUT; i += stride) {
        size_t k = i / DOUT, o = i % DOUT;
        g_WlinT[i] = Wlin[o * H + k];
    }
    for (size_t i = tid; i < G; i += stride) {
        g_b0[i] = bih0[i] + bhh0[i];
        g_b1[i] = bih1[i] + bhh1[i];
    }
    for (size_t i = tid; i < H * B; i += stride) {
        size_t u = i >> 6, b = i & 63;
        float zv = z[b * H + u];
        g_h0[0][i] = zv;
        g_h1[0][i] = zv;
    }
}

// ---------------- xproj: g_xp[t][n][b] = b0[n] + x[b][t-1][:] . Wih0T[:][n] ----------------
__global__ __launch_bounds__(256) void xproj_kernel(const float* __restrict__ x) {
    int t = blockIdx.y;
    int n0 = blockIdx.x * 64;
    int tid = threadIdx.x;
    int w = tid >> 5, l = tid & 31;

    __shared__ float sh[64][64];
    float acc0[8], acc1[8];
#pragma unroll
    for (int i = 0; i < 8; i++) { acc0[i] = 0.0f; acc1[i] = 0.0f; }

    if (t > 0) {
        for (int k0 = 0; k0 < DIN; k0 += 64) {
            __syncthreads();
#pragma unroll
            for (int r = 0; r < 4; r++) {
                int v = tid + 256 * r;
                int b = v >> 4, kq = v & 15;
                *(float4*)&sh[b][kq * 4] =
                    *(const float4*)&x[((size_t)b * T + (t - 1)) * DIN + k0 + kq * 4];
            }
            __syncthreads();
#pragma unroll 8
            for (int kk = 0; kk < 64; kk++) {
                const float* wr = &g_Wih0T[(size_t)(k0 + kk) * G + n0];
                float wa = wr[l];
                float wb = wr[32 + l];
#pragma unroll
                for (int i = 0; i < 8; i++) {
                    float a = sh[w * 8 + i][kk];
                    acc0[i] += wa * a;
                    acc1[i] += wb * a;
                }
            }
        }
    }
    float ba = g_b0[n0 + l], bb = g_b0[n0 + 32 + l];
#pragma unroll
    for (int i = 0; i < 8; i++) { acc0[i] += ba; acc1[i] += bb; }
    float4 v;
    size_t basea = ((size_t)t * G + n0 + l) * B + w * 8;
    v = make_float4(acc0[0], acc0[1], acc0[2], acc0[3]); *(float4*)&g_xp[basea] = v;
    v = make_float4(acc0[4], acc0[5], acc0[6], acc0[7]); *(float4*)&g_xp[basea + 4] = v;
    size_t baseb = ((size_t)t * G + n0 + 32 + l) * B + w * 8;
    v = make_float4(acc1[0], acc1[1], acc1[2], acc1[3]); *(float4*)&g_xp[baseb] = v;
    v = make_float4(acc1[4], acc1[5], acc1[6], acc1[7]); *(float4*)&g_xp[baseb + 4] = v;
}

// ---------------- persistent recurrent kernel ----------------
__device__ __forceinline__ void grid_sync(unsigned target) {
    __syncthreads();
    if (threadIdx.x == 0) {
        __threadfence();
        if (atomicAdd(&g_bar_cnt, 1u) == NBLK - 1) {
            g_bar_cnt = 0;
            __threadfence();
            g_bar_gen = target;
        } else {
            while (g_bar_gen < target) {}
            __threadfence();
        }
    }
    __syncthreads();
}

// 8 cols x 8 batches per thread, 16 k-rows (this warp's slice of the 128-row chunk)
#define COL(wv, o) { ull wq = pack2(wv, wv); \
    acc[(o) + 0] = fma2(wq, x0.x, acc[(o) + 0]); \
    acc[(o) + 1] = fma2(wq, x0.y, acc[(o) + 1]); \
    acc[(o) + 2] = fma2(wq, x1.x, acc[(o) + 2]); \
    acc[(o) + 3] = fma2(wq, x1.y, acc[(o) + 3]); }

__device__ __forceinline__ void compute_chunk(const float* __restrict__ act_c,
                                              const float* __restrict__ wt_c,
                                              int kbase, int cg8, int bg8,
                                              ull* acc) {
#pragma unroll 8
    for (int kk = 0; kk < 16; kk++) {
        int k = kbase + kk;
        const float4* wp = (const float4*)&wt_c[k * 32 + cg8];
        float4 w0 = wp[0];
        float4 w1 = wp[1];
        const ulonglong2* ap = (const ulonglong2*)&act_c[k * 64 + bg8];
        ulonglong2 x0 = ap[0];
        ulonglong2 x1 = ap[1];
        COL(w0.x, 0)  COL(w0.y, 4)  COL(w0.z, 8)  COL(w0.w, 12)
        COL(w1.x, 16) COL(w1.y, 20) COL(w1.z, 24) COL(w1.w, 28)
    }
}

__global__ void __launch_bounds__(THR, 1) recur_kernel() {
    extern __shared__ float smem[];
    unsigned sb = (unsigned)__cvta_generic_to_shared(smem);
    unsigned bar0 = sb + BAR_BYTE_OFF;
    unsigned bar1 = bar0 + 8;
    float* part = smem + PART_OFF;

    int tid = threadIdx.x;
    int blk = blockIdx.x;
    int kg = tid >> 5, lane = tid & 31;
    int cg8 = (lane & 3) * 8;       // col group offset (0,8,16,24)
    int bg8 = (lane >> 2) * 8;      // batch group offset (0..56)
    int kbase = kg * 16;
    int u0 = blk * 8;

    // gate-phase ownership: 2 (unit,batch) items per thread
    int u_[2], b_[2];
    float b1v[2][4];
#pragma unroll
    for (int j = 0; j < 2; j++) {
        int item = tid + j * THR;
        u_[j] = item >> 6;
        b_[j] = item & 63;
#pragma unroll
        for (int g = 0; g < 4; g++)
            b1v[j][g] = g_b1[g * H + u0 + u_[j]];
    }

    if (tid == 0) {
        mbar_init(bar0, 1);
        mbar_init(bar1, 1);
        asm volatile("fence.proxy.async.shared::cta;" ::: "memory");
    }
    __syncthreads();

    unsigned ph0 = 0, ph1 = 0;
    float c0r[2] = {0.0f, 0.0f};
    float c1r[2] = {0.0f, 0.0f};

    const float* w0base = &g_Wq0[(size_t)blk * H * 32];
    const float* w1base = &g_Wq1[(size_t)blk * 2 * H * 32];

    for (int t = 0; t < T; t++) {
        int cur = t & 1, nxt = cur ^ 1;
        const float* h0cur = g_h0[cur];

        // ================= layer 0 (8 chunks of 128 k) =================
        if (tid == 0) {
            mbar_expect_tx(bar0, 49152u);
            bulk_cp(sb + ACT_OFF * 4, h0cur, 32768u, bar0);
            bulk_cp(sb + WT_OFF * 4, w0base, 16384u, bar0);
        }
        ull acc[32];
#pragma unroll
        for (int i = 0; i < 32; i++) acc[i] = 0ull;

        for (int ch = 0; ch < 8; ch++) {
            int buf = ch & 1;
            if (tid == 0 && ch + 1 < 8) {
                unsigned bb = buf ? bar0 : bar1;
                int nb = buf ^ 1;
                mbar_expect_tx(bb, 49152u);
                bulk_cp(sb + (ACT_OFF + nb * 8192) * 4, h0cur + (size_t)(ch + 1) * 8192, 32768u, bb);
                bulk_cp(sb + (WT_OFF + nb * 4096) * 4, w0base + (size_t)(ch + 1) * 4096, 16384u, bb);
            }
            if (buf == 0) { mbar_wait(bar0, ph0); ph0 ^= 1; }
            else          { mbar_wait(bar1, ph1); ph1 ^= 1; }
            compute_chunk(smem + ACT_OFF + buf * 8192, smem + WT_OFF + buf * 4096,
                          kbase, cg8, bg8, acc);
            __syncthreads();
        }
        // store partials: part[kg][c][b]
#pragma unroll
        for (int ci = 0; ci < 8; ci++)
#pragma unroll
            for (int bp = 0; bp < 4; bp++)
                *(ull*)&part[kg * 2048 + (cg8 + ci) * 64 + bg8 + bp * 2] = acc[ci * 4 + bp];
        __syncthreads();
        // reduce + gates (layer0)
#pragma unroll
        for (int j = 0; j < 2; j++) {
            int u = u_[j], b = b_[j];
            float gv[4];
#pragma unroll
            for (int g = 0; g < 4; g++) {
                float s = 0.0f;
#pragma unroll
                for (int kgi = 0; kgi < 8; kgi++)
                    s += part[kgi * 2048 + (g * 8 + u) * 64 + b];
                gv[g] = s + g_xp[((size_t)t * G + g * H + u0 + u) * B + b];
            }
            float cc = sigm(gv[1]) * c0r[j] + sigm(gv[0]) * tanh_f(gv[2]);
            c0r[j] = cc;
            g_h0[nxt][(u0 + u) * B + b] = sigm(gv[3]) * tanh_f(cc);
        }
        grid_sync(2 * t + 1);

        // ================= layer 1 (16 chunks of 128 k) =================
        const float* h0n = g_h0[nxt];
        const float* h1o = g_h1[cur];
        if (tid == 0) {
            mbar_expect_tx(bar0, 49152u);
            bulk_cp(sb + ACT_OFF * 4, h0n, 32768u, bar0);
            bulk_cp(sb + WT_OFF * 4, w1base, 16384u, bar0);
        }
#pragma unroll
        for (int i = 0; i < 32; i++) acc[i] = 0ull;

        for (int ch = 0; ch < 16; ch++) {
            int buf = ch & 1;
            if (tid == 0 && ch + 1 < 16) {
                unsigned bb = buf ? bar0 : bar1;
                int nb = buf ^ 1;
                int nc = ch + 1;
                const float* src = (nc < 8) ? (h0n + (size_t)nc * 8192)
                                            : (h1o + (size_t)(nc - 8) * 8192);
                mbar_expect_tx(bb, 49152u);
                bulk_cp(sb + (ACT_OFF + nb * 8192) * 4, src, 32768u, bb);
                bulk_cp(sb + (WT_OFF + nb * 4096) * 4, w1base + (size_t)nc * 4096, 16384u, bb);
            }
            if (buf == 0) { mbar_wait(bar0, ph0); ph0 ^= 1; }
            else          { mbar_wait(bar1, ph1); ph1 ^= 1; }
            compute_chunk(smem + ACT_OFF + buf * 8192, smem + WT_OFF + buf * 4096,
                          kbase, cg8, bg8, acc);
            __syncthreads();
        }
#pragma unroll
        for (int ci = 0; ci < 8; ci++)
#pragma unroll
            for (int bp = 0; bp < 4; bp++)
                *(ull*)&part[kg * 2048 + (cg8 + ci) * 64 + bg8 + bp * 2] = acc[ci * 4 + bp];
        __syncthreads();
#pragma unroll
        for (int j = 0; j < 2; j++) {
            int u = u_[j], b = b_[j];
            float gv[4];
#pragma unroll
            for (int g = 0; g < 4; g++) {
                float s = b1v[j][g];
#pragma unroll
                for (int kgi = 0; kgi < 8; kgi++)
                    s += part[kgi * 2048 + (g * 8 + u) * 64 + b];
                gv[g] = s;
            }
            float cc = sigm(gv[1]) * c1r[j] + sigm(gv[0]) * tanh_f(gv[2]);
            c1r[j] = cc;
            float h = sigm(gv[3]) * tanh_f(cc);
            int idx = (u0 + u) * B + b;
            g_h1[nxt][idx] = h;
            g_h1buf[(size_t)t * H * B + idx] = h;
        }
        grid_sync(2 * t + 2);
    }
}

// ---------------- out: out[b][t][o] = blin[o] + sum_k h1buf[t][k][b] * WlinT[k][o] ----------------
__global__ __launch_bounds__(256) void out_kernel(const float* __restrict__ blin,
                                                  float* __restrict__ out) {
    int t = blockIdx.y;
    int o0 = blockIdx.x * 64;
    int tid = threadIdx.x;
    int w = tid >> 5, l = tid & 31;

    __shared__ float sh[64 * 64];   // [k][b]
    float acc0[8], acc1[8];
#pragma unroll
    for (int i = 0; i < 8; i++) { acc0[i] = 0.0f; acc1[i] = 0.0f; }

    for (int k0 = 0; k0 < H; k0 += 64) {
        __syncthreads();
#pragma unroll
        for (int r = 0; r < 4; r++) {
            int idx = tid + r * 256;
            ((float4*)sh)[idx] =
                *(((const float4*)&g_h1buf[((size_t)t * H + k0) * B]) + idx);
        }
        __syncthreads();
#pragma unroll 8
        for (int kk = 0; kk < 64; kk++) {
            const float* wr = &g_WlinT[(size_t)(k0 + kk) * DOUT + o0];
            float wa = wr[l];
            float wb = wr[32 + l];
#pragma unroll
            for (int i = 0; i < 8; i++) {
                float av = sh[kk * 64 + w * 8 + i];
                acc0[i] += wa * av;
                acc1[i] += wb * av;
            }
        }
    }
    float ba = blin[o0 + l], bb = blin[o0 + 32 + l];
#pragma unroll
    for (int i = 0; i < 8; i++) {
        int b = w * 8 + i;
        size_t base = ((size_t)b * T + t) * DOUT + o0;
        out[base + l] = acc0[i] + ba;
        out[base + 32 + l] = acc1[i] + bb;
    }
}

// ---------------- launch ----------------
extern "C" void kernel_launch(void* const* d_in, const int* in_sizes, int n_in,
                              void* d_out, int out_size) {
    const float* z    = (const float*)d_in[0];
    const float* x    = (const float*)d_in[1];
    const float* Wih0 = (const float*)d_in[2];
    const float* Whh0 = (const float*)d_in[3];
    const float* bih0 = (const float*)d_in[4];
    const float* bhh0 = (const float*)d_in[5];
    const float* Wih1 = (const float*)d_in[6];
    const float* Whh1 = (const float*)d_in[7];
    const float* bih1 = (const float*)d_in[8];
    const float* bhh1 = (const float*)d_in[9];
    const float* Wlin = (const float*)d_in[10];
    const float* blin = (const float*)d_in[11];
    float* out = (float*)d_out;

    cudaFuncSetAttribute(recur_kernel, cudaFuncAttributeMaxDynamicSharedMemorySize,
                         SMEM_BYTES);

    prep_kernel<<<512, 256>>>(z, Wih0, Whh0, bih0, bhh0, Wih1, Whh1, bih1, bhh1, Wlin);
    xproj_kernel<<<dim3(G / 64, T), 256>>>(x);
    recur_kernel<<<NBLK, THR, SMEM_BYTES>>>();
    out_kernel<<<dim3(DOUT / 64, T), 256>>>(blin, out);
}

// round 9
// speedup vs baseline: 15.7289x; 1.6549x over previous
#include <cuda_runtime.h>
#include <cuda_bf16.h>

#define B    64
#define T    512
#define DIN  256
#define H    1024
#define G    4096   // 4*H
#define DOUT 256
#define NBLK 128
#define THR  256

typedef unsigned long long ull;

// SMEM byte layout
#define S_ACT   0                 // 2 bufs x 32768 B
#define S_WT    65536             // 2 bufs x 16384 B
#define S_SG    98304             // 4 slices x 2112 floats = 33792 B
#define S_BAR   132096
#define SMEM_BYTES (132096 + 16)

// ---------------- device scratch ----------------
__device__ float g_Wih0T[(size_t)DIN * G];        // [k][n] for xproj
__device__ __align__(128) unsigned short g_Wf0[(size_t)NBLK * 8 * 8192];   // frag-packed bf16 hi/lo
__device__ __align__(128) unsigned short g_Wf1[(size_t)NBLK * 16 * 8192];
__device__ float g_WlinT[(size_t)H * DOUT];       // [k][o]
__device__ float g_b0[G];
__device__ float g_b1[G];
__device__ float g_xp[(size_t)T * G * B];         // [t][n][b]
__device__ __align__(128) unsigned short g_h0f[2][131072];  // frag bf16: 8 chunks x (16KB hi + 16KB lo)
__device__ __align__(128) unsigned short g_h1f[2][131072];
__device__ float g_h1buf[(size_t)T * H * B];      // [t][k][b] fp32 for out

__device__ volatile unsigned g_bar_gen;
__device__ unsigned g_bar_cnt;

// ---------------- helpers ----------------
__device__ __forceinline__ float sigm(float x) { return 1.0f / (1.0f + __expf(-x)); }
__device__ __forceinline__ float tanh_f(float x) {
    float e = __expf(-2.0f * fabsf(x));
    float t = (1.0f - e) / (1.0f + e);
    return x >= 0.0f ? t : -t;
}
__device__ __forceinline__ void mbar_init(unsigned mbar, unsigned cnt) {
    asm volatile("mbarrier.init.shared.b64 [%0], %1;" :: "r"(mbar), "r"(cnt) : "memory");
}
__device__ __forceinline__ void mbar_expect_tx(unsigned mbar, unsigned bytes) {
    asm volatile("mbarrier.arrive.expect_tx.shared.b64 _, [%0], %1;" :: "r"(mbar), "r"(bytes) : "memory");
}
__device__ __forceinline__ void mbar_wait(unsigned mbar, unsigned phase) {
    asm volatile(
        "{\n\t"
        ".reg .pred P;\n\t"
        "WAIT_%=:\n\t"
        "mbarrier.try_wait.parity.acquire.cta.shared::cta.b64 P, [%0], %1, 0x989680;\n\t"
        "@P bra.uni DONE_%=;\n\t"
        "bra.uni WAIT_%=;\n\t"
        "DONE_%=:\n\t"
        "}"
        :: "r"(mbar), "r"(phase) : "memory");
}
__device__ __forceinline__ void bulk_cp(unsigned dst, const void* src, unsigned bytes, unsigned mbar) {
    asm volatile(
        "cp.async.bulk.shared::cluster.global.mbarrier::complete_tx::bytes [%0], [%1], %2, [%3];"
        :: "r"(dst), "l"(src), "r"(bytes), "r"(mbar) : "memory");
}
__device__ __forceinline__ void mma16816(float4& d, const uint4& a, unsigned b0, unsigned b1) {
    asm volatile("mma.sync.aligned.m16n8k16.row.col.f32.bf16.bf16.f32 "
                 "{%0,%1,%2,%3}, {%4,%5,%6,%7}, {%8,%9}, {%0,%1,%2,%3};"
                 : "+f"(d.x), "+f"(d.y), "+f"(d.z), "+f"(d.w)
                 : "r"(a.x), "r"(a.y), "r"(a.z), "r"(a.w), "r"(b0), "r"(b1));
}

// store fp32 h value as A-fragment bf16 hi/lo pair (byte-addressed target array)
__device__ __forceinline__ void store_frag_pair(unsigned char* basearr, int uGlob, int b, float v) {
    int chunk = uGlob >> 7, kl = uGlob & 127;
    int kt = kl >> 4, kk = kl & 15;
    int mt = b >> 4, mm = b & 15;
    int reg = ((kk & 8) >> 2) | ((mm & 8) >> 3);        // (kk>=8)*2 + (mm>=8)
    int lane = (mm & 7) * 4 + ((kk & 7) >> 1);
    int half = kk & 1;
    int off = kt * 2048 + mt * 512 + lane * 16 + reg * 4 + half * 2;
    __nv_bfloat16 hb = __float2bfloat16_rn(v);
    float hf = __bfloat162float(hb);
    __nv_bfloat16 lb = __float2bfloat16_rn(v - hf);
    unsigned char* p = basearr + (size_t)chunk * 32768 + off;
    *(__nv_bfloat16*)p = hb;
    *(__nv_bfloat16*)(p + 16384) = lb;
}

// ---------------- prep ----------------
__global__ void prep_kernel(const float* __restrict__ z,
                            const float* __restrict__ Wih0, const float* __restrict__ Whh0,
                            const float* __restrict__ bih0, const float* __restrict__ bhh0,
                            const float* __restrict__ Wih1, const float* __restrict__ Whh1,
                            const float* __restrict__ bih1, const float* __restrict__ bhh1,
                            const float* __restrict__ Wlin) {
    size_t stride = (size_t)gridDim.x * blockDim.x;
    size_t tid = (size_t)blockIdx.x * blockDim.x + threadIdx.x;
    if (tid == 0) { g_bar_gen = 0; g_bar_cnt = 0; }

    for (size_t i = tid; i < (size_t)DIN * G; i += stride) {
        size_t k = i / G, n = i % G;
        g_Wih0T[i] = Wih0[n * DIN + k];
    }
    // layer0 frag weights: dst index e decomposes to fragment coordinates
    for (size_t e = tid; e < (size_t)NBLK * 8 * 8192; e += stride) {
        int half = e & 1;
        int slotq = (e >> 1) & 3;
        int lane = (e >> 3) & 31;
        int hl = (e >> 8) & 1;
        int nt = (e >> 9) & 1;
        int kt = (e >> 10) & 7;
        int chunk = (e >> 13) & 7;
        size_t blk = e >> 16;
        int n8sel = slotq >> 1, kHi = slotq & 1;
        int nn = lane >> 2, tig = lane & 3;
        int kk = kHi * 8 + tig * 2 + half;
        int k = chunk * 128 + kt * 16 + kk;
        int cc = nt * 16 + n8sel * 8 + nn;
        size_t n = (size_t)(cc >> 3) * H + blk * 8 + (cc & 7);
        float w = Whh0[n * H + k];
        __nv_bfloat16 hb = __float2bfloat16_rn(w);
        __nv_bfloat16 outv = hb;
        if (hl) outv = __float2bfloat16_rn(w - __bfloat162float(hb));
        g_Wf0[e] = *(unsigned short*)&outv;
    }
    // layer1 frag weights (K = 2048: first h0, then h1)
    for (size_t e = tid; e < (size_t)NBLK * 16 * 8192; e += stride) {
        int half = e & 1;
        int slotq = (e >> 1) & 3;
        int lane = (e >> 3) & 31;
        int hl = (e >> 8) & 1;
        int nt = (e >> 9) & 1;
        int kt = (e >> 10) & 7;
        int chunk = (e >> 13) & 15;
        size_t blk = e >> 17;
        int n8sel = slotq >> 1, kHi = slotq & 1;
        int nn = lane >> 2, tig = lane & 3;
        int kk = kHi * 8 + tig * 2 + half;
        int k = chunk * 128 + kt * 16 + kk;
        int cc = nt * 16 + n8sel * 8 + nn;
        size_t n = (size_t)(cc >> 3) * H + blk * 8 + (cc & 7);
        float w = (k < H) ? Wih1[n * H + k] : Whh1[n * H + (k - H)];
        __nv_bfloat16 hb = __float2bfloat16_rn(w);
        __nv_bfloat16 outv = hb;
        if (hl) outv = __float2bfloat16_rn(w - __bfloat162float(hb));
        g_Wf1[e] = *(unsigned short*)&outv;
    }
    for (size_t i = tid; i < (size_t)H * DOUT; i += stride) {
        size_t k = i / DOUT, o = i % DOUT;
        g_WlinT[i] = Wlin[o * H + k];
    }
    for (size_t i = tid; i < G; i += stride) {
        g_b0[i] = bih0[i] + bhh0[i];
        g_b1[i] = bih1[i] + bhh1[i];
    }
    for (size_t i = tid; i < H * B; i += stride) {
        int u = i >> 6, b = i & 63;
        float zv = z[(size_t)b * H + u];
        store_frag_pair((unsigned char*)g_h0f[0], u, b, zv);
        store_frag_pair((unsigned char*)g_h1f[0], u, b, zv);
    }
}

// ---------------- xproj ----------------
__global__ __launch_bounds__(256) void xproj_kernel(const float* __restrict__ x) {
    int t = blockIdx.y;
    int n0 = blockIdx.x * 64;
    int tid = threadIdx.x;
    int w = tid >> 5, l = tid & 31;

    __shared__ float sh[64][64];
    float acc0[8], acc1[8];
#pragma unroll
    for (int i = 0; i < 8; i++) { acc0[i] = 0.0f; acc1[i] = 0.0f; }

    if (t > 0) {
        for (int k0 = 0; k0 < DIN; k0 += 64) {
            __syncthreads();
#pragma unroll
            for (int r = 0; r < 4; r++) {
                int v = tid + 256 * r;
                int b = v >> 4, kq = v & 15;
                *(float4*)&sh[b][kq * 4] =
                    *(const float4*)&x[((size_t)b * T + (t - 1)) * DIN + k0 + kq * 4];
            }
            __syncthreads();
#pragma unroll 8
            for (int kk = 0; kk < 64; kk++) {
                const float* wr = &g_Wih0T[(size_t)(k0 + kk) * G + n0];
                float wa = wr[l];
                float wb = wr[32 + l];
#pragma unroll
                for (int i = 0; i < 8; i++) {
                    float a = sh[w * 8 + i][kk];
                    acc0[i] += wa * a;
                    acc1[i] += wb * a;
                }
            }
        }
    }
    float ba = g_b0[n0 + l], bb = g_b0[n0 + 32 + l];
#pragma unroll
    for (int i = 0; i < 8; i++) { acc0[i] += ba; acc1[i] += bb; }
    float4 v;
    size_t basea = ((size_t)t * G + n0 + l) * B + w * 8;
    v = make_float4(acc0[0], acc0[1], acc0[2], acc0[3]); *(float4*)&g_xp[basea] = v;
    v = make_float4(acc0[4], acc0[5], acc0[6], acc0[7]); *(float4*)&g_xp[basea + 4] = v;
    size_t baseb = ((size_t)t * G + n0 + 32 + l) * B + w * 8;
    v = make_float4(acc1[0], acc1[1], acc1[2], acc1[3]); *(float4*)&g_xp[baseb] = v;
    v = make_float4(acc1[4], acc1[5], acc1[6], acc1[7]); *(float4*)&g_xp[baseb + 4] = v;
}

// ---------------- persistent recurrent kernel ----------------
__device__ __forceinline__ void grid_sync(unsigned target) {
    __syncthreads();
    if (threadIdx.x == 0) {
        __threadfence();
        if (atomicAdd(&g_bar_cnt, 1u) == NBLK - 1) {
            g_bar_cnt = 0;
            __threadfence();
            g_bar_gen = target;
        } else {
            while (g_bar_gen < target) {}
            __threadfence();
        }
    }
    __syncthreads();
}

// one k16-step: warp tile m32 x n32, split-bf16 (3 MMA products)
__device__ __forceinline__ void mma_kt(const unsigned char* actb, const unsigned char* wtb,
                                       int kt, int mgroup, int lane, float4 (&c)[2][4]) {
    const unsigned char* ab = actb + kt * 2048 + lane * 16;
    uint4 ah0 = *(const uint4*)(ab + (mgroup * 2 + 0) * 512);
    uint4 ah1 = *(const uint4*)(ab + (mgroup * 2 + 1) * 512);
    uint4 al0 = *(const uint4*)(ab + 16384 + (mgroup * 2 + 0) * 512);
    uint4 al1 = *(const uint4*)(ab + 16384 + (mgroup * 2 + 1) * 512);
    const unsigned char* wb = wtb + kt * 2048 + lane * 16;
    uint4 bh0 = *(const uint4*)(wb);           // nt0 hi: n8#0 (x,y), n8#1 (z,w)
    uint4 bl0 = *(const uint4*)(wb + 512);     // nt0 lo
    uint4 bh1 = *(const uint4*)(wb + 1024);    // nt1 hi: n8#2, n8#3
    uint4 bl1 = *(const uint4*)(wb + 1536);    // nt1 lo
    // hi * hi
    mma16816(c[0][0], ah0, bh0.x, bh0.y);  mma16816(c[1][0], ah1, bh0.x, bh0.y);
    mma16816(c[0][1], ah0, bh0.z, bh0.w);  mma16816(c[1][1], ah1, bh0.z, bh0.w);
    mma16816(c[0][2], ah0, bh1.x, bh1.y);  mma16816(c[1][2], ah1, bh1.x, bh1.y);
    mma16816(c[0][3], ah0, bh1.z, bh1.w);  mma16816(c[1][3], ah1, bh1.z, bh1.w);
    // hi * lo
    mma16816(c[0][0], ah0, bl0.x, bl0.y);  mma16816(c[1][0], ah1, bl0.x, bl0.y);
    mma16816(c[0][1], ah0, bl0.z, bl0.w);  mma16816(c[1][1], ah1, bl0.z, bl0.w);
    mma16816(c[0][2], ah0, bl1.x, bl1.y);  mma16816(c[1][2], ah1, bl1.x, bl1.y);
    mma16816(c[0][3], ah0, bl1.z, bl1.w);  mma16816(c[1][3], ah1, bl1.z, bl1.w);
    // lo * hi
    mma16816(c[0][0], al0, bh0.x, bh0.y);  mma16816(c[1][0], al1, bh0.x, bh0.y);
    mma16816(c[0][1], al0, bh0.z, bh0.w);  mma16816(c[1][1], al1, bh0.z, bh0.w);
    mma16816(c[0][2], al0, bh1.x, bh1.y);  mma16816(c[1][2], al1, bh1.x, bh1.y);
    mma16816(c[0][3], al0, bh1.z, bh1.w);  mma16816(c[1][3], al1, bh1.z, bh1.w);
}

__global__ void __launch_bounds__(THR, 1) recur_kernel() {
    extern __shared__ unsigned char smem[];
    unsigned sb = (unsigned)__cvta_generic_to_shared(smem);
    unsigned bar0 = sb + S_BAR;
    unsigned bar1 = bar0 + 8;
    float* sg4 = (float*)(smem + S_SG);

    int tid = threadIdx.x;
    int blk = blockIdx.x;
    int wrp = tid >> 5, lane = tid & 31;
    int ks = wrp & 3;          // K-split slice: handles kt = ks, ks+4
    int mgroup = wrp >> 2;     // batches mgroup*32 .. +31
    int u0 = blk * 8;

    // gate-phase ownership: 2 (unit,batch) items per thread
    int u_[2], b_[2];
    float b1v[2][4];
#pragma unroll
    for (int j = 0; j < 2; j++) {
        int item = tid + j * THR;
        u_[j] = item >> 6;
        b_[j] = item & 63;
#pragma unroll
        for (int g = 0; g < 4; g++)
            b1v[j][g] = g_b1[g * H + u0 + u_[j]];
    }

    if (tid == 0) {
        mbar_init(bar0, 1);
        mbar_init(bar1, 1);
        asm volatile("fence.proxy.async.shared::cta;" ::: "memory");
    }
    __syncthreads();

    unsigned ph0 = 0, ph1 = 0;
    float c0r[2] = {0.0f, 0.0f};
    float c1r[2] = {0.0f, 0.0f};

    const unsigned char* wf0base = (const unsigned char*)&g_Wf0[(size_t)blk * 8 * 8192];
    const unsigned char* wf1base = (const unsigned char*)&g_Wf1[(size_t)blk * 16 * 8192];

    for (int t = 0; t < T; t++) {
        int cur = t & 1, nxt = cur ^ 1;
        const unsigned char* h0cur = (const unsigned char*)g_h0f[cur];

        // ================= layer 0 (8 chunks of K=128) =================
        if (tid == 0) {
            mbar_expect_tx(bar0, 49152u);
            bulk_cp(sb + S_ACT, h0cur, 32768u, bar0);
            bulk_cp(sb + S_WT, wf0base, 16384u, bar0);
        }
        float4 cacc[2][4];
#pragma unroll
        for (int i = 0; i < 2; i++)
#pragma unroll
            for (int j = 0; j < 4; j++) cacc[i][j] = make_float4(0.f, 0.f, 0.f, 0.f);

        for (int ch = 0; ch < 8; ch++) {
            int buf = ch & 1;
            if (tid == 0 && ch + 1 < 8) {
                unsigned bb = buf ? bar0 : bar1;
                int nb = buf ^ 1;
                mbar_expect_tx(bb, 49152u);
                bulk_cp(sb + S_ACT + nb * 32768, h0cur + (size_t)(ch + 1) * 32768, 32768u, bb);
                bulk_cp(sb + S_WT + nb * 16384, wf0base + (size_t)(ch + 1) * 16384, 16384u, bb);
            }
            if (buf == 0) { mbar_wait(bar0, ph0); ph0 ^= 1; }
            else          { mbar_wait(bar1, ph1); ph1 ^= 1; }
            const unsigned char* actb = smem + S_ACT + buf * 32768;
            const unsigned char* wtb  = smem + S_WT + buf * 16384;
            mma_kt(actb, wtb, ks, mgroup, lane, cacc);
            mma_kt(actb, wtb, ks + 4, mgroup, lane, cacc);
            __syncthreads();
        }
        // stage accumulators to sg4[ks]
        {
            float* sgS = sg4 + ks * 2112;
#pragma unroll
            for (int mt = 0; mt < 2; mt++)
#pragma unroll
                for (int j = 0; j < 4; j++) {
                    float4 v = cacc[mt][j];
                    int row0 = mgroup * 32 + mt * 16 + (lane >> 2);
                    int colb = j * 8 + (lane & 3) * 2;
                    sgS[row0 * 33 + colb] = v.x;
                    sgS[row0 * 33 + colb + 1] = v.y;
                    sgS[(row0 + 8) * 33 + colb] = v.z;
                    sgS[(row0 + 8) * 33 + colb + 1] = v.w;
                }
        }
        __syncthreads();
#pragma unroll
        for (int j = 0; j < 2; j++) {
            int u = u_[j], b = b_[j];
            float gv[4];
#pragma unroll
            for (int g = 0; g < 4; g++) {
                float s = g_xp[((size_t)t * G + g * H + u0 + u) * B + b];
#pragma unroll
                for (int sI = 0; sI < 4; sI++)
                    s += sg4[sI * 2112 + b * 33 + g * 8 + u];
                gv[g] = s;
            }
            float cc = sigm(gv[1]) * c0r[j] + sigm(gv[0]) * tanh_f(gv[2]);
            c0r[j] = cc;
            float h = sigm(gv[3]) * tanh_f(cc);
            store_frag_pair((unsigned char*)g_h0f[nxt], u0 + u, b, h);
        }
        grid_sync(2 * t + 1);

        // ================= layer 1 (16 chunks of K=128) =================
        const unsigned char* h0n = (const unsigned char*)g_h0f[nxt];
        const unsigned char* h1o = (const unsigned char*)g_h1f[cur];
        if (tid == 0) {
            mbar_expect_tx(bar0, 49152u);
            bulk_cp(sb + S_ACT, h0n, 32768u, bar0);
            bulk_cp(sb + S_WT, wf1base, 16384u, bar0);
        }
#pragma unroll
        for (int i = 0; i < 2; i++)
#pragma unroll
            for (int j = 0; j < 4; j++) cacc[i][j] = make_float4(0.f, 0.f, 0.f, 0.f);

        for (int ch = 0; ch < 16; ch++) {
            int buf = ch & 1;
            if (tid == 0 && ch + 1 < 16) {
                unsigned bb = buf ? bar0 : bar1;
                int nb = buf ^ 1;
                int nc = ch + 1;
                const unsigned char* src = (nc < 8) ? (h0n + (size_t)nc * 32768)
                                                    : (h1o + (size_t)(nc - 8) * 32768);
                mbar_expect_tx(bb, 49152u);
                bulk_cp(sb + S_ACT + nb * 32768, src, 32768u, bb);
                bulk_cp(sb + S_WT + nb * 16384, wf1base + (size_t)nc * 16384, 16384u, bb);
            }
            if (buf == 0) { mbar_wait(bar0, ph0); ph0 ^= 1; }
            else          { mbar_wait(bar1, ph1); ph1 ^= 1; }
            const unsigned char* actb = smem + S_ACT + buf * 32768;
            const unsigned char* wtb  = smem + S_WT + buf * 16384;
            mma_kt(actb, wtb, ks, mgroup, lane, cacc);
            mma_kt(actb, wtb, ks + 4, mgroup, lane, cacc);
            __syncthreads();
        }
        {
            float* sgS = sg4 + ks * 2112;
#pragma unroll
            for (int mt = 0; mt < 2; mt++)
#pragma unroll
                for (int j = 0; j < 4; j++) {
                    float4 v = cacc[mt][j];
                    int row0 = mgroup * 32 + mt * 16 + (lane >> 2);
                    int colb = j * 8 + (lane & 3) * 2;
                    sgS[row0 * 33 + colb] = v.x;
                    sgS[row0 * 33 + colb + 1] = v.y;
                    sgS[(row0 + 8) * 33 + colb] = v.z;
                    sgS[(row0 + 8) * 33 + colb + 1] = v.w;
                }
        }
        __syncthreads();
#pragma unroll
        for (int j = 0; j < 2; j++) {
            int u = u_[j], b = b_[j];
            float gv[4];
#pragma unroll
            for (int g = 0; g < 4; g++) {
                float s = b1v[j][g];
#pragma unroll
                for (int sI = 0; sI < 4; sI++)
                    s += sg4[sI * 2112 + b * 33 + g * 8 + u];
                gv[g] = s;
            }
            float cc = sigm(gv[1]) * c1r[j] + sigm(gv[0]) * tanh_f(gv[2]);
            c1r[j] = cc;
            float h = sigm(gv[3]) * tanh_f(cc);
            store_frag_pair((unsigned char*)g_h1f[nxt], u0 + u, b, h);
            g_h1buf[(size_t)t * H * B + (u0 + u) * B + b] = h;
        }
        grid_sync(2 * t + 2);
    }
}

// ---------------- out: out[b][t][o] = blin[o] + sum_k h1buf[t][k][b] * WlinT[k][o] ----------------
__global__ __launch_bounds__(256) void out_kernel(const float* __restrict__ blin,
                                                  float* __restrict__ out) {
    int t = blockIdx.y;
    int o0 = blockIdx.x * 64;
    int tid = threadIdx.x;
    int w = tid >> 5, l = tid & 31;

    __shared__ float sh[64 * 64];   // [k][b]
    float acc0[8], acc1[8];
#pragma unroll
    for (int i = 0; i < 8; i++) { acc0[i] = 0.0f; acc1[i] = 0.0f; }

    for (int k0 = 0; k0 < H; k0 += 64) {
        __syncthreads();
#pragma unroll
        for (int r = 0; r < 4; r++) {
            int idx = tid + r * 256;
            ((float4*)sh)[idx] =
                *(((const float4*)&g_h1buf[((size_t)t * H + k0) * B]) + idx);
        }
        __syncthreads();
#pragma unroll 8
        for (int kk = 0; kk < 64; kk++) {
            const float* wr = &g_WlinT[(size_t)(k0 + kk) * DOUT + o0];
            float wa = wr[l];
            float wb = wr[32 + l];
#pragma unroll
            for (int i = 0; i < 8; i++) {
                float av = sh[kk * 64 + w * 8 + i];
                acc0[i] += wa * av;
                acc1[i] += wb * av;
            }
        }
    }
    float ba = blin[o0 + l], bb = blin[o0 + 32 + l];
#pragma unroll
    for (int i = 0; i < 8; i++) {
        int b = w * 8 + i;
        size_t base = ((size_t)b * T + t) * DOUT + o0;
        out[base + l] = acc0[i] + ba;
        out[base + 32 + l] = acc1[i] + bb;
    }
}

// ---------------- launch ----------------
extern "C" void kernel_launch(void* const* d_in, const int* in_sizes, int n_in,
                              void* d_out, int out_size) {
    const float* z    = (const float*)d_in[0];
    const float* x    = (const float*)d_in[1];
    const float* Wih0 = (const float*)d_in[2];
    const float* Whh0 = (const float*)d_in[3];
    const float* bih0 = (const float*)d_in[4];
    const float* bhh0 = (const float*)d_in[5];
    const float* Wih1 = (const float*)d_in[6];
    const float* Whh1 = (const float*)d_in[7];
    const float* bih1 = (const float*)d_in[8];
    const float* bhh1 = (const float*)d_in[9];
    const float* Wlin = (const float*)d_in[10];
    const float* blin = (const float*)d_in[11];
    float* out = (float*)d_out;

    cudaFuncSetAttribute(recur_kernel, cudaFuncAttributeMaxDynamicSharedMemorySize,
                         SMEM_BYTES);

    prep_kernel<<<512, 256>>>(z, Wih0, Whh0, bih0, bhh0, Wih1, Whh1, bih1, bhh1, Wlin);
    xproj_kernel<<<dim3(G / 64, T), 256>>>(x);
    recur_kernel<<<NBLK, THR, SMEM_BYTES>>>();
    out_kernel<<<dim3(DOUT / 64, T), 256>>>(blin, out);
}

// round 10
// speedup vs baseline: 19.3450x; 1.2299x over previous
#include <cuda_runtime.h>
#include <cuda_bf16.h>

#define B    64
#define T    512
#define DIN  256
#define H    1024
#define G    4096   // 4*H
#define DOUT 256
#define NBLK 128
#define THR  256

typedef unsigned long long ull;
typedef unsigned char uchar;

// ---------------- recur SMEM byte layout: 3 stages x (32KB act + 16KB wt) ----------------
#define S_STAGE  49152
#define S_SG     147456              // 4 slices x 2112 floats = 33792 B
#define S_BAR    181248              // 3 mbarriers
#define SMEM_BYTES 181280

// ---------------- xproj SMEM byte layout ----------------
#define XS_A    0                    // 2 chunks x 32768
#define XS_W    65536                // 2 ngrp x (2 chunks x 16384)
#define XS_S    131072               // 2 slices x 4416 floats = 35328 B
#define XS_BAR  166400
#define XSMEM_BYTES 166432

// ---------------- device scratch ----------------
__device__ __align__(128) unsigned short g_Wf0[(size_t)NBLK * 8 * 8192];   // layer0 frag bf16 hi/lo
__device__ __align__(128) unsigned short g_Wf1[(size_t)NBLK * 16 * 8192];  // layer1
__device__ __align__(128) unsigned short g_WxF[(size_t)128 * 2 * 8192];    // xproj weights frag
__device__ __align__(128) unsigned short g_xf[(size_t)T * 32768];          // x frag: per t, 2 chunks x 32KB
__device__ float g_WlinT[(size_t)H * DOUT];       // [k][o]
__device__ float g_b0[G];
__device__ float g_b1[G];
__device__ float g_xp[(size_t)T * G * B];         // [t][n][b]
__device__ __align__(128) unsigned short g_h0f[2][131072];  // frag bf16: 8 chunks x (16KB hi + 16KB lo)
__device__ __align__(128) unsigned short g_h1f[2][131072];
__device__ float g_h1buf[(size_t)T * H * B];      // [t][u][b] fp32 for out

__device__ volatile unsigned g_bar_gen;
__device__ unsigned g_bar_cnt;

// ---------------- helpers ----------------
__device__ __forceinline__ float sigm(float x) { return 1.0f / (1.0f + __expf(-x)); }
__device__ __forceinline__ float tanh_f(float x) {
    float e = __expf(-2.0f * fabsf(x));
    float t = (1.0f - e) / (1.0f + e);
    return x >= 0.0f ? t : -t;
}
__device__ __forceinline__ void mbar_init(unsigned mbar, unsigned cnt) {
    asm volatile("mbarrier.init.shared.b64 [%0], %1;" :: "r"(mbar), "r"(cnt) : "memory");
}
__device__ __forceinline__ void mbar_expect_tx(unsigned mbar, unsigned bytes) {
    asm volatile("mbarrier.arrive.expect_tx.shared.b64 _, [%0], %1;" :: "r"(mbar), "r"(bytes) : "memory");
}
__device__ __forceinline__ void mbar_wait(unsigned mbar, unsigned phase) {
    asm volatile(
        "{\n\t"
        ".reg .pred P;\n\t"
        "WAIT_%=:\n\t"
        "mbarrier.try_wait.parity.acquire.cta.shared::cta.b64 P, [%0], %1, 0x989680;\n\t"
        "@P bra.uni DONE_%=;\n\t"
        "bra.uni WAIT_%=;\n\t"
        "DONE_%=:\n\t"
        "}"
        :: "r"(mbar), "r"(phase) : "memory");
}
__device__ __forceinline__ void bulk_cp(unsigned dst, const void* src, unsigned bytes, unsigned mbar) {
    asm volatile(
        "cp.async.bulk.shared::cluster.global.mbarrier::complete_tx::bytes [%0], [%1], %2, [%3];"
        :: "r"(dst), "l"(src), "r"(bytes), "r"(mbar) : "memory");
}
__device__ __forceinline__ void mma16816(float4& d, const uint4& a, unsigned b0, unsigned b1) {
    asm volatile("mma.sync.aligned.m16n8k16.row.col.f32.bf16.bf16.f32 "
                 "{%0,%1,%2,%3}, {%4,%5,%6,%7}, {%8,%9}, {%0,%1,%2,%3};"
                 : "+f"(d.x), "+f"(d.y), "+f"(d.z), "+f"(d.w)
                 : "r"(a.x), "r"(a.y), "r"(a.z), "r"(a.w), "r"(b0), "r"(b1));
}

// store fp32 value as A-fragment bf16 hi/lo pair
__device__ __forceinline__ void store_frag_pair(uchar* basearr, int uGlob, int b, float v) {
    int chunk = uGlob >> 7, kl = uGlob & 127;
    int kt = kl >> 4, kk = kl & 15;
    int mt = b >> 4, mm = b & 15;
    int reg = ((kk & 8) >> 2) | ((mm & 8) >> 3);
    int lane = (mm & 7) * 4 + ((kk & 7) >> 1);
    int half = kk & 1;
    int off = kt * 2048 + mt * 512 + lane * 16 + reg * 4 + half * 2;
    __nv_bfloat16 hb = __float2bfloat16_rn(v);
    float hf = __bfloat162float(hb);
    __nv_bfloat16 lb = __float2bfloat16_rn(v - hf);
    uchar* p = basearr + (size_t)chunk * 32768 + off;
    *(__nv_bfloat16*)p = hb;
    *(__nv_bfloat16*)(p + 16384) = lb;
}

// one k16-step: warp tile m32 x n32, split-bf16 (3 MMA products)
__device__ __forceinline__ void mma_kt(const uchar* actb, const uchar* wtb,
                                       int kt, int mgroup, int lane, float4 (&c)[2][4]) {
    const uchar* ab = actb + kt * 2048 + lane * 16;
    uint4 ah0 = *(const uint4*)(ab + (mgroup * 2 + 0) * 512);
    uint4 ah1 = *(const uint4*)(ab + (mgroup * 2 + 1) * 512);
    uint4 al0 = *(const uint4*)(ab + 16384 + (mgroup * 2 + 0) * 512);
    uint4 al1 = *(const uint4*)(ab + 16384 + (mgroup * 2 + 1) * 512);
    const uchar* wb = wtb + kt * 2048 + lane * 16;
    uint4 bh0 = *(const uint4*)(wb);
    uint4 bl0 = *(const uint4*)(wb + 512);
    uint4 bh1 = *(const uint4*)(wb + 1024);
    uint4 bl1 = *(const uint4*)(wb + 1536);
    mma16816(c[0][0], ah0, bh0.x, bh0.y);  mma16816(c[1][0], ah1, bh0.x, bh0.y);
    mma16816(c[0][1], ah0, bh0.z, bh0.w);  mma16816(c[1][1], ah1, bh0.z, bh0.w);
    mma16816(c[0][2], ah0, bh1.x, bh1.y);  mma16816(c[1][2], ah1, bh1.x, bh1.y);
    mma16816(c[0][3], ah0, bh1.z, bh1.w);  mma16816(c[1][3], ah1, bh1.z, bh1.w);
    mma16816(c[0][0], ah0, bl0.x, bl0.y);  mma16816(c[1][0], ah1, bl0.x, bl0.y);
    mma16816(c[0][1], ah0, bl0.z, bl0.w);  mma16816(c[1][1], ah1, bl0.z, bl0.w);
    mma16816(c[0][2], ah0, bl1.x, bl1.y);  mma16816(c[1][2], ah1, bl1.x, bl1.y);
    mma16816(c[0][3], ah0, bl1.z, bl1.w);  mma16816(c[1][3], ah1, bl1.z, bl1.w);
    mma16816(c[0][0], al0, bh0.x, bh0.y);  mma16816(c[1][0], al1, bh0.x, bh0.y);
    mma16816(c[0][1], al0, bh0.z, bh0.w);  mma16816(c[1][1], al1, bh0.z, bh0.w);
    mma16816(c[0][2], al0, bh1.x, bh1.y);  mma16816(c[1][2], al1, bh1.x, bh1.y);
    mma16816(c[0][3], al0, bh1.z, bh1.w);  mma16816(c[1][3], al1, bh1.z, bh1.w);
}

// ---------------- prep ----------------
__global__ void prep_kernel(const float* __restrict__ z, const float* __restrict__ x,
                            const float* __restrict__ Wih0, const float* __restrict__ Whh0,
                            const float* __restrict__ bih0, const float* __restrict__ bhh0,
                            const float* __restrict__ Wih1, const float* __restrict__ Whh1,
                            const float* __restrict__ bih1, const float* __restrict__ bhh1,
                            const float* __restrict__ Wlin) {
    size_t stride = (size_t)gridDim.x * blockDim.x;
    size_t tid = (size_t)blockIdx.x * blockDim.x + threadIdx.x;
    if (tid == 0) { g_bar_gen = 0; g_bar_cnt = 0; }

    // layer0 frag weights
    for (size_t e = tid; e < (size_t)NBLK * 8 * 8192; e += stride) {
        int half = e & 1;
        int slotq = (e >> 1) & 3;
        int lane = (e >> 3) & 31;
        int hl = (e >> 8) & 1;
        int nt = (e >> 9) & 1;
        int kt = (e >> 10) & 7;
        int chunk = (e >> 13) & 7;
        size_t blk = e >> 16;
        int n8sel = slotq >> 1, kHi = slotq & 1;
        int nn = lane >> 2, tig = lane & 3;
        int kk = kHi * 8 + tig * 2 + half;
        int k = chunk * 128 + kt * 16 + kk;
        int cc = nt * 16 + n8sel * 8 + nn;
        size_t n = (size_t)(cc >> 3) * H + blk * 8 + (cc & 7);
        float w = Whh0[n * H + k];
        __nv_bfloat16 hb = __float2bfloat16_rn(w);
        __nv_bfloat16 outv = hb;
        if (hl) outv = __float2bfloat16_rn(w - __bfloat162float(hb));
        g_Wf0[e] = *(unsigned short*)&outv;
    }
    // layer1 frag weights (K = 2048: first h0, then h1)
    for (size_t e = tid; e < (size_t)NBLK * 16 * 8192; e += stride) {
        int half = e & 1;
        int slotq = (e >> 1) & 3;
        int lane = (e >> 3) & 31;
        int hl = (e >> 8) & 1;
        int nt = (e >> 9) & 1;
        int kt = (e >> 10) & 7;
        int chunk = (e >> 13) & 15;
        size_t blk = e >> 17;
        int n8sel = slotq >> 1, kHi = slotq & 1;
        int nn = lane >> 2, tig = lane & 3;
        int kk = kHi * 8 + tig * 2 + half;
        int k = chunk * 128 + kt * 16 + kk;
        int cc = nt * 16 + n8sel * 8 + nn;
        size_t n = (size_t)(cc >> 3) * H + blk * 8 + (cc & 7);
        float w = (k < H) ? Wih1[n * H + k] : Whh1[n * H + (k - H)];
        __nv_bfloat16 hb = __float2bfloat16_rn(w);
        __nv_bfloat16 outv = hb;
        if (hl) outv = __float2bfloat16_rn(w - __bfloat162float(hb));
        g_Wf1[e] = *(unsigned short*)&outv;
    }
    // xproj frag weights: [nb32(128)][chunk(2)][8192]
    for (size_t e = tid; e < (size_t)128 * 2 * 8192; e += stride) {
        int half = e & 1;
        int slotq = (e >> 1) & 3;
        int lane = (e >> 3) & 31;
        int hl = (e >> 8) & 1;
        int nt = (e >> 9) & 1;
        int kt = (e >> 10) & 7;
        int chunk = (e >> 13) & 1;
        size_t nb32 = e >> 14;
        int n8sel = slotq >> 1, kHi = slotq & 1;
        int nn = lane >> 2, tig = lane & 3;
        int kk = kHi * 8 + tig * 2 + half;
        int k = chunk * 128 + kt * 16 + kk;
        size_t n = nb32 * 32 + nt * 16 + n8sel * 8 + nn;
        float w = Wih0[n * DIN + k];
        __nv_bfloat16 hb = __float2bfloat16_rn(w);
        __nv_bfloat16 outv = hb;
        if (hl) outv = __float2bfloat16_rn(w - __bfloat162float(hb));
        g_WxF[e] = *(unsigned short*)&outv;
    }
    // x frag pack: i = (b*T + tx)*256 + k  (coalesced x reads)
    for (size_t i = tid; i < (size_t)T * B * DIN; i += stride) {
        int k = i & 255;
        int tx = (i >> 8) & (T - 1);
        int b = i >> 17;
        store_frag_pair((uchar*)g_xf + (size_t)tx * 65536, k, b, x[i]);
    }
    for (size_t i = tid; i < (size_t)H * DOUT; i += stride) {
        size_t k = i / DOUT, o = i % DOUT;
        g_WlinT[i] = Wlin[o * H + k];
    }
    for (size_t i = tid; i < G; i += stride) {
        g_b0[i] = bih0[i] + bhh0[i];
        g_b1[i] = bih1[i] + bhh1[i];
    }
    for (size_t i = tid; i < H * B; i += stride) {
        int u = i >> 6, b = i & 63;
        float zv = z[(size_t)b * H + u];
        store_frag_pair((uchar*)g_h0f[0], u, b, zv);
        store_frag_pair((uchar*)g_h1f[0], u, b, zv);
    }
}

// ---------------- xproj (tensor-core): xp[t][n][b] = b0[n] + x[b][t-1] . Wih0^T ----------------
__global__ void __launch_bounds__(256, 1) xproj_kernel() {
    extern __shared__ uchar xs[];
    int t = blockIdx.y;
    int nb = blockIdx.x;             // 64-col group
    int tid = threadIdx.x;

    if (t == 0) {   // zero input step: bias only
        int n_local = tid >> 2, bb = (tid & 3) * 16;
        float bv = g_b0[nb * 64 + n_local];
        float4 v = make_float4(bv, bv, bv, bv);
        float4* dst = (float4*)&g_xp[(size_t)(nb * 64 + n_local) * B + bb];
        dst[0] = v; dst[1] = v; dst[2] = v; dst[3] = v;
        return;
    }

    unsigned sb = (unsigned)__cvta_generic_to_shared(xs);
    unsigned bar = sb + XS_BAR;
    if (tid == 0) {
        mbar_init(bar, 1);
        asm volatile("fence.proxy.async.shared::cta;" ::: "memory");
    }
    __syncthreads();
    if (tid == 0) {
        mbar_expect_tx(bar, 131072u);
        bulk_cp(sb + XS_A, (const uchar*)g_xf + (size_t)(t - 1) * 65536, 65536u, bar);
        bulk_cp(sb + XS_W, (const uchar*)g_WxF + (size_t)nb * 65536, 65536u, bar);
    }
    mbar_wait(bar, 0);

    int wid = tid >> 5, lane = tid & 31;
    int ksx = wid & 1, ngrp = (wid >> 1) & 1, mgrp = wid >> 2;
    float4 cacc[2][4];
#pragma unroll
    for (int i = 0; i < 2; i++)
#pragma unroll
        for (int j = 0; j < 4; j++) cacc[i][j] = make_float4(0.f, 0.f, 0.f, 0.f);

    const uchar* actb = xs + XS_A + ksx * 32768;
    const uchar* wtb  = xs + XS_W + ngrp * 32768 + ksx * 16384;
#pragma unroll
    for (int kt = 0; kt < 8; kt++)
        mma_kt(actb, wtb, kt, mgrp, lane, cacc);

    // stage [b][n] per k-slice, stride 69
    float* sgx = (float*)(xs + XS_S) + ksx * 4416;
#pragma unroll
    for (int mt = 0; mt < 2; mt++)
#pragma unroll
        for (int j = 0; j < 4; j++) {
            float4 v = cacc[mt][j];
            int row0 = mgrp * 32 + mt * 16 + (lane >> 2);
            int col = ngrp * 32 + j * 8 + (lane & 3) * 2;
            sgx[row0 * 69 + col] = v.x;
            sgx[row0 * 69 + col + 1] = v.y;
            sgx[(row0 + 8) * 69 + col] = v.z;
            sgx[(row0 + 8) * 69 + col + 1] = v.w;
        }
    __syncthreads();

    const float* sg0 = (const float*)(xs + XS_S);
    const float* sg1 = sg0 + 4416;
    int n_local = tid >> 2, bb = (tid & 3) * 16;
    float bv = g_b0[nb * 64 + n_local];
    float* dst = &g_xp[((size_t)t * G + nb * 64 + n_local) * B + bb];
#pragma unroll
    for (int q = 0; q < 4; q++) {
        float4 v;
        v.x = sg0[(bb + q * 4 + 0) * 69 + n_local] + sg1[(bb + q * 4 + 0) * 69 + n_local] + bv;
        v.y = sg0[(bb + q * 4 + 1) * 69 + n_local] + sg1[(bb + q * 4 + 1) * 69 + n_local] + bv;
        v.z = sg0[(bb + q * 4 + 2) * 69 + n_local] + sg1[(bb + q * 4 + 2) * 69 + n_local] + bv;
        v.w = sg0[(bb + q * 4 + 3) * 69 + n_local] + sg1[(bb + q * 4 + 3) * 69 + n_local] + bv;
        ((float4*)dst)[q] = v;
    }
}

// ---------------- persistent recurrent kernel ----------------
__device__ __forceinline__ void grid_sync(unsigned target) {
    __syncthreads();
    if (threadIdx.x == 0) {
        __threadfence();
        if (atomicAdd(&g_bar_cnt, 1u) == NBLK - 1) {
            g_bar_cnt = 0;
            __threadfence();
            g_bar_gen = target;
        } else {
            while (g_bar_gen < target) {}
            __threadfence();
        }
    }
    __syncthreads();
}

__device__ __forceinline__ void issue_stage(unsigned sb, int stage,
                                            const uchar* act, const uchar* wt) {
    unsigned bar = sb + S_BAR + stage * 8;
    mbar_expect_tx(bar, 49152u);
    bulk_cp(sb + stage * S_STAGE, act, 32768u, bar);
    bulk_cp(sb + stage * S_STAGE + 32768, wt, 16384u, bar);
}

__device__ __forceinline__ void chunk_src(int i, const uchar* h0src, const uchar* h1src,
                                          const uchar* wf0base, const uchar* wf1base,
                                          const uchar*& act, const uchar*& wt) {
    if (i < 16) {   // layer1 chunk
        act = (i < 8) ? h0src + (size_t)i * 32768 : h1src + (size_t)(i - 8) * 32768;
        wt = wf1base + (size_t)i * 16384;
    } else {        // layer0 (next step) chunk
        act = h0src + (size_t)(i - 16) * 32768;
        wt = wf0base + (size_t)(i - 16) * 16384;
    }
}

__global__ void __launch_bounds__(THR, 1) recur_kernel() {
    extern __shared__ uchar smem[];
    unsigned sb = (unsigned)__cvta_generic_to_shared(smem);
    float* sg4 = (float*)(smem + S_SG);

    int tid = threadIdx.x;
    int blk = blockIdx.x;
    int wrp = tid >> 5, lane = tid & 31;
    int ks = wrp & 3;          // K-split slice: handles kt = ks, ks+4
    int mgroup = wrp >> 2;     // batches mgroup*32 .. +31
    int u0 = blk * 8;

    // gate-phase ownership: 2 (unit,batch) items per thread
    int u_[2], b_[2];
    float b1v[2][4];
#pragma unroll
    for (int j = 0; j < 2; j++) {
        int item = tid + j * THR;
        u_[j] = item >> 6;
        b_[j] = item & 63;
#pragma unroll
        for (int g = 0; g < 4; g++)
            b1v[j][g] = g_b1[g * H + u0 + u_[j]];
    }

    if (tid == 0) {
        mbar_init(sb + S_BAR, 1);
        mbar_init(sb + S_BAR + 8, 1);
        mbar_init(sb + S_BAR + 16, 1);
        asm volatile("fence.proxy.async.shared::cta;" ::: "memory");
    }
    __syncthreads();

    unsigned ph_bits = 0;      // per-stage phase parity
    float c0r[2] = {0.0f, 0.0f};
    float c1r[2] = {0.0f, 0.0f};

    const uchar* wf0base = (const uchar*)&g_Wf0[(size_t)blk * 8 * 8192];
    const uchar* wf1base = (const uchar*)&g_Wf1[(size_t)blk * 16 * 8192];

    float4 acc0[2][4], acc1[2][4];

    // ================= prologue: L0(0) =================
    {
        const uchar* h00 = (const uchar*)g_h0f[0];
        if (tid == 0) {
            issue_stage(sb, 0, h00, wf0base);
            issue_stage(sb, 1, h00 + 32768, wf0base + 16384);
        }
#pragma unroll
        for (int i = 0; i < 2; i++)
#pragma unroll
            for (int j = 0; j < 4; j++) acc0[i][j] = make_float4(0.f, 0.f, 0.f, 0.f);
        for (int i = 0; i < 8; i++) {
            int stage = i % 3;
            if (tid == 0 && i + 2 < 8)
                issue_stage(sb, (i + 2) % 3, h00 + (size_t)(i + 2) * 32768,
                            wf0base + (size_t)(i + 2) * 16384);
            mbar_wait(sb + S_BAR + stage * 8, (ph_bits >> stage) & 1);
            ph_bits ^= 1u << stage;
            const uchar* actb = smem + stage * S_STAGE;
            const uchar* wtb = actb + 32768;
            mma_kt(actb, wtb, ks, mgroup, lane, acc0);
            mma_kt(actb, wtb, ks + 4, mgroup, lane, acc0);
            __syncthreads();
        }
        // L0(0) gates -> h0f[1]
        float* sgS = sg4 + ks * 2112;
#pragma unroll
        for (int mt = 0; mt < 2; mt++)
#pragma unroll
            for (int j = 0; j < 4; j++) {
                float4 v = acc0[mt][j];
                int row0 = mgroup * 32 + mt * 16 + (lane >> 2);
                int colb = j * 8 + (lane & 3) * 2;
                sgS[row0 * 33 + colb] = v.x;
                sgS[row0 * 33 + colb + 1] = v.y;
                sgS[(row0 + 8) * 33 + colb] = v.z;
                sgS[(row0 + 8) * 33 + colb + 1] = v.w;
            }
        __syncthreads();
#pragma unroll
        for (int j = 0; j < 2; j++) {
            int u = u_[j], b = b_[j];
            float gv[4];
#pragma unroll
            for (int g = 0; g < 4; g++) {
                float s = g_xp[((size_t)0 * G + g * H + u0 + u) * B + b];
#pragma unroll
                for (int sI = 0; sI < 4; sI++)
                    s += sg4[sI * 2112 + b * 33 + g * 8 + u];
                gv[g] = s;
            }
            float cc = sigm(gv[1]) * c0r[j] + sigm(gv[0]) * tanh_f(gv[2]);
            c0r[j] = cc;
            float h = sigm(gv[3]) * tanh_f(cc);
            store_frag_pair((uchar*)g_h0f[1], u0 + u, b, h);
        }
    }

    // ================= main loop: one grid sync per step =================
    for (int t = 0; t < T; t++) {
        grid_sync(t + 1);
        const uchar* h0src = (const uchar*)g_h0f[(t + 1) & 1];  // h0(t), input to L1(t) and L0(t+1)
        const uchar* h1src = (const uchar*)g_h1f[t & 1];        // h1(t-1)
        int NCH = (t == T - 1) ? 16 : 24;

        if (tid == 0) {
            const uchar *a0, *w0, *a1, *w1;
            chunk_src(0, h0src, h1src, wf0base, wf1base, a0, w0);
            chunk_src(1, h0src, h1src, wf0base, wf1base, a1, w1);
            issue_stage(sb, 0, a0, w0);
            issue_stage(sb, 1, a1, w1);
        }
#pragma unroll
        for (int i = 0; i < 2; i++)
#pragma unroll
            for (int j = 0; j < 4; j++) {
                acc1[i][j] = make_float4(0.f, 0.f, 0.f, 0.f);
                acc0[i][j] = make_float4(0.f, 0.f, 0.f, 0.f);
            }

        for (int i = 0; i < NCH; i++) {
            int stage = i % 3;
            if (tid == 0 && i + 2 < NCH) {
                const uchar *an, *wn;
                chunk_src(i + 2, h0src, h1src, wf0base, wf1base, an, wn);
                issue_stage(sb, (i + 2) % 3, an, wn);
            }
            mbar_wait(sb + S_BAR + stage * 8, (ph_bits >> stage) & 1);
            ph_bits ^= 1u << stage;
            const uchar* actb = smem + stage * S_STAGE;
            const uchar* wtb = actb + 32768;
            if (i < 16) {
                mma_kt(actb, wtb, ks, mgroup, lane, acc1);
                mma_kt(actb, wtb, ks + 4, mgroup, lane, acc1);
            } else {
                mma_kt(actb, wtb, ks, mgroup, lane, acc0);
                mma_kt(actb, wtb, ks + 4, mgroup, lane, acc0);
            }
            __syncthreads();
        }

        // ---- L1(t) gates -> h1f[(t+1)&1], h1buf[t] ----
        {
            float* sgS = sg4 + ks * 2112;
#pragma unroll
            for (int mt = 0; mt < 2; mt++)
#pragma unroll
                for (int j = 0; j < 4; j++) {
                    float4 v = acc1[mt][j];
                    int row0 = mgroup * 32 + mt * 16 + (lane >> 2);
                    int colb = j * 8 + (lane & 3) * 2;
                    sgS[row0 * 33 + colb] = v.x;
                    sgS[row0 * 33 + colb + 1] = v.y;
                    sgS[(row0 + 8) * 33 + colb] = v.z;
                    sgS[(row0 + 8) * 33 + colb + 1] = v.w;
                }
        }
        __syncthreads();
#pragma unroll
        for (int j = 0; j < 2; j++) {
            int u = u_[j], b = b_[j];
            float gv[4];
#pragma unroll
            for (int g = 0; g < 4; g++) {
                float s = b1v[j][g];
#pragma unroll
                for (int sI = 0; sI < 4; sI++)
                    s += sg4[sI * 2112 + b * 33 + g * 8 + u];
                gv[g] = s;
            }
            float cc = sigm(gv[1]) * c1r[j] + sigm(gv[0]) * tanh_f(gv[2]);
            c1r[j] = cc;
            float h = sigm(gv[3]) * tanh_f(cc);
            store_frag_pair((uchar*)g_h1f[(t + 1) & 1], u0 + u, b, h);
            g_h1buf[(size_t)t * H * B + (u0 + u) * B + b] = h;
        }
        if (t + 1 >= T) break;
        __syncthreads();

        // ---- L0(t+1) gates -> h0f[t&1] ----
        {
            float* sgS = sg4 + ks * 2112;
#pragma unroll
            for (int mt = 0; mt < 2; mt++)
#pragma unroll
                for (int j = 0; j < 4; j++) {
                    float4 v = acc0[mt][j];
                    int row0 = mgroup * 32 + mt * 16 + (lane >> 2);
                    int colb = j * 8 + (lane & 3) * 2;
                    sgS[row0 * 33 + colb] = v.x;
                    sgS[row0 * 33 + colb + 1] = v.y;
                    sgS[(row0 + 8) * 33 + colb] = v.z;
                    sgS[(row0 + 8) * 33 + colb + 1] = v.w;
                }
        }
        __syncthreads();
#pragma unroll
        for (int j = 0; j < 2; j++) {
            int u = u_[j], b = b_[j];
            float gv[4];
#pragma unroll
            for (int g = 0; g < 4; g++) {
                float s = g_xp[((size_t)(t + 1) * G + g * H + u0 + u) * B + b];
#pragma unroll
                for (int sI = 0; sI < 4; sI++)
                    s += sg4[sI * 2112 + b * 33 + g * 8 + u];
                gv[g] = s;
            }
            float cc = sigm(gv[1]) * c0r[j] + sigm(gv[0]) * tanh_f(gv[2]);
            c0r[j] = cc;
            float h = sigm(gv[3]) * tanh_f(cc);
            store_frag_pair((uchar*)g_h0f[t & 1], u0 + u, b, h);
        }
    }
}

// ---------------- out: out[b][t][o] = blin[o] + sum_k h1buf[t][k][b] * WlinT[k][o] ----------------
__global__ __launch_bounds__(256) void out_kernel(const float* __restrict__ blin,
                                                  float* __restrict__ out) {
    int t = blockIdx.y;
    int o0 = blockIdx.x * 64;
    int tid = threadIdx.x;
    int w = tid >> 5, l = tid & 31;

    __shared__ float sh[64 * 64];   // [k][b]
    float acc0[8], acc1[8];
#pragma unroll
    for (int i = 0; i < 8; i++) { acc0[i] = 0.0f; acc1[i] = 0.0f; }

    for (int k0 = 0; k0 < H; k0 += 64) {
        __syncthreads();
#pragma unroll
        for (int r = 0; r < 4; r++) {
            int idx = tid + r * 256;
            ((float4*)sh)[idx] =
                *(((const float4*)&g_h1buf[((size_t)t * H + k0) * B]) + idx);
        }
        __syncthreads();
#pragma unroll 8
        for (int kk = 0; kk < 64; kk++) {
            const float* wr = &g_WlinT[(size_t)(k0 + kk) * DOUT + o0];
            float wa = wr[l];
            float wb = wr[32 + l];
#pragma unroll
            for (int i = 0; i < 8; i++) {
                float av = sh[kk * 64 + w * 8 + i];
                acc0[i] += wa * av;
                acc1[i] += wb * av;
            }
        }
    }
    float ba = blin[o0 + l], bb = blin[o0 + 32 + l];
#pragma unroll
    for (int i = 0; i < 8; i++) {
        int b = w * 8 + i;
        size_t base = ((size_t)b * T + t) * DOUT + o0;
        out[base + l] = acc0[i] + ba;
        out[base + 32 + l] = acc1[i] + bb;
    }
}

// ---------------- launch ----------------
extern "C" void kernel_launch(void* const* d_in, const int* in_sizes, int n_in,
                              void* d_out, int out_size) {
    const float* z    = (const float*)d_in[0];
    const float* x    = (const float*)d_in[1];
    const float* Wih0 = (const float*)d_in[2];
    const float* Whh0 = (const float*)d_in[3];
    const float* bih0 = (const float*)d_in[4];
    const float* bhh0 = (const float*)d_in[5];
    const float* Wih1 = (const float*)d_in[6];
    const float* Whh1 = (const float*)d_in[7];
    const float* bih1 = (const float*)d_in[8];
    const float* bhh1 = (const float*)d_in[9];
    const float* Wlin = (const float*)d_in[10];
    const float* blin = (const float*)d_in[11];
    float* out = (float*)d_out;

    cudaFuncSetAttribute(recur_kernel, cudaFuncAttributeMaxDynamicSharedMemorySize,
                         SMEM_BYTES);
    cudaFuncSetAttribute(xproj_kernel, cudaFuncAttributeMaxDynamicSharedMemorySize,
                         XSMEM_BYTES);

    prep_kernel<<<512, 256>>>(z, x, Wih0, Whh0, bih0, bhh0, Wih1, Whh1, bih1, bhh1, Wlin);
    xproj_kernel<<<dim3(G / 64, T), 256, XSMEM_BYTES>>>();
    recur_kernel<<<NBLK, THR, SMEM_BYTES>>>();
    out_kernel<<<dim3(DOUT / 64, T), 256>>>(blin, out);
}